// round 2
// baseline (speedup 1.0000x reference)
#include <cuda_runtime.h>
#include <math.h>

// ---------------- problem constants ----------------
#define N_PIX  16384          // 128*128 spatial
#define BATCH  8
#define CDIM   256
#define INNER  512            // HEADS*DIM_HEAD
#define NHEADS 8
#define DHEAD  64

// ---------------- scratch (static device globals; no allocation) ----------------
__device__ __align__(16) float g_dw  [(size_t)BATCH * CDIM  * N_PIX];   // depthwise conv out
__device__ __align__(16) float g_q   [(size_t)BATCH * INNER * N_PIX];   // q (then softmaxed)
__device__ __align__(16) float g_kv  [(size_t)BATCH * 2*INNER * N_PIX]; // k (ch 0..511), v (512..1023)
__device__ __align__(16) float g_av  [(size_t)BATCH * INNER * N_PIX];   // gelu(q@ctx)
__device__ __align__(16) float g_part[64 * 8 * 64 * 64];                // split-K context partials
__device__ __align__(16) float g_ctx [64 * 64 * 64];                    // per-(b,h) ctx^T  [e][d]

__device__ __forceinline__ float gelu_exact(float x) { return x * normcdff(x); }

// ---------------- depthwise 3x3, pad 1 ----------------
__global__ void __launch_bounds__(256) k_dwconv(const float* __restrict__ in,
                                                const float* __restrict__ wdw)
{
    int plane = blockIdx.y;              // b*256 + c
    int c     = plane & 255;
    const float* ip = in   + (size_t)plane * N_PIX;
    float*       op = g_dw + (size_t)plane * N_PIX;

    float w[9];
#pragma unroll
    for (int k = 0; k < 9; ++k) w[k] = __ldg(wdw + c * 9 + k);

    int p = blockIdx.x * 256 + threadIdx.x;      // 0..16383
    int y = p >> 7, x = p & 127;
    float s = 0.f;
#pragma unroll
    for (int dy = -1; dy <= 1; ++dy) {
        int yy = y + dy;
        if (yy < 0 || yy > 127) continue;
#pragma unroll
        for (int dx = -1; dx <= 1; ++dx) {
            int xx = x + dx;
            if (xx < 0 || xx > 127) continue;
            s += ip[yy * 128 + xx] * w[(dy + 1) * 3 + (dx + 1)];
        }
    }
    op[p] = s;
}

// ---------------- generic channel-major GEMM ----------------
// Y[o, p] = sum_c W[o, c] * X[c, p]     (X rows contiguous in p; W row-major [O, C])
// Batched over blockIdx.z with element strides xs/ws/ys. Optional GELU on output, bias add.
// Block: 128 pixels x BN outs, BK=8, 256 threads, per-thread 8 x (BN/16).
template <int BN, bool GELU_OUT, bool BIAS>
__global__ void __launch_bounds__(256) k_gemm(
    const float* __restrict__ X, const float* __restrict__ W,
    const float* __restrict__ bias, float* __restrict__ Y,
    int C, int N, long long xs, long long ws, long long ys)
{
    constexpr int BM = 128, BK = 8;
    constexpr int TN = BN / 16;          // 8 or 4

    __shared__ __align__(16) float Xs[BK][BM];
    __shared__ __align__(16) float Ws[BK][BN];

    const float* Xb = X + (long long)blockIdx.z * xs;
    const float* Wb = W + (long long)blockIdx.z * ws;
    float*       Yb = Y + (long long)blockIdx.z * ys;

    const int p0 = blockIdx.x * BM;
    const int o0 = blockIdx.y * BN;
    const int t  = threadIdx.x;
    const int tm = t & 15;               // pixel group
    const int tn = t >> 4;               // output group

    float acc[8][TN];
#pragma unroll
    for (int i = 0; i < 8; ++i)
#pragma unroll
        for (int j = 0; j < TN; ++j) acc[i][j] = 0.f;

    for (int c0 = 0; c0 < C; c0 += BK) {
        // --- load X tile: BK x BM  (exactly 256 float4) ---
        {
            int kk = t >> 5, p4 = t & 31;
            float4 xv = *(const float4*)(Xb + (size_t)(c0 + kk) * N + p0 + p4 * 4);
            *(float4*)&Xs[kk][p4 * 4] = xv;
        }
        // --- load W tile: BN x BK, transposed to Ws[k][o] ---
        for (int i = t; i < BN * BK / 4; i += 256) {
            int o = i >> 1, cq = i & 1;  // BK/4 == 2
            float4 wv = *(const float4*)(Wb + (size_t)(o0 + o) * C + c0 + cq * 4);
            Ws[cq * 4 + 0][o] = wv.x;
            Ws[cq * 4 + 1][o] = wv.y;
            Ws[cq * 4 + 2][o] = wv.z;
            Ws[cq * 4 + 3][o] = wv.w;
        }
        __syncthreads();

#pragma unroll
        for (int kk = 0; kk < BK; ++kk) {
            float a[8], b[TN];
#pragma unroll
            for (int cm = 0; cm < 2; ++cm) {
                float4 av = *(const float4*)&Xs[kk][tm * 4 + cm * 64];
                a[cm * 4 + 0] = av.x; a[cm * 4 + 1] = av.y;
                a[cm * 4 + 2] = av.z; a[cm * 4 + 3] = av.w;
            }
#pragma unroll
            for (int cn = 0; cn < TN / 4; ++cn) {
                float4 bv = *(const float4*)&Ws[kk][tn * 4 + cn * 64];
                b[cn * 4 + 0] = bv.x; b[cn * 4 + 1] = bv.y;
                b[cn * 4 + 2] = bv.z; b[cn * 4 + 3] = bv.w;
            }
#pragma unroll
            for (int i = 0; i < 8; ++i)
#pragma unroll
                for (int j = 0; j < TN; ++j)
                    acc[i][j] += a[i] * b[j];
        }
        __syncthreads();
    }

    // --- epilogue ---
#pragma unroll
    for (int cn = 0; cn < TN / 4; ++cn) {
#pragma unroll
        for (int j = 0; j < 4; ++j) {
            int o = o0 + tn * 4 + cn * 64 + j;
            float bb = 0.f;
            if (BIAS) bb = __ldg(&bias[o]);
#pragma unroll
            for (int cm = 0; cm < 2; ++cm) {
                float4 v;
                v.x = acc[cm * 4 + 0][cn * 4 + j] + bb;
                v.y = acc[cm * 4 + 1][cn * 4 + j] + bb;
                v.z = acc[cm * 4 + 2][cn * 4 + j] + bb;
                v.w = acc[cm * 4 + 3][cn * 4 + j] + bb;
                if (GELU_OUT) {
                    v.x = gelu_exact(v.x); v.y = gelu_exact(v.y);
                    v.z = gelu_exact(v.z); v.w = gelu_exact(v.w);
                }
                *(float4*)(Yb + (size_t)o * N + p0 + tm * 4 + cm * 64) = v;
            }
        }
    }
}

// ---------------- softmax over feature dim d (64) for q, then * scale ----------------
// q layout [B][512][N]; group = channels h*64 .. h*64+63 at fixed (b, n)
__global__ void __launch_bounds__(256) k_softmax_q(float* __restrict__ q)
{
    int idx = blockIdx.x * 256 + threadIdx.x;      // 8*8*16384 items
    int n   = idx & (N_PIX - 1);
    int bh  = idx >> 14;
    int b   = bh >> 3, h = bh & 7;
    float* base = q + ((size_t)b * INNER + (size_t)h * 64) * N_PIX + n;

    float v[64];
    float m = -3.4e38f;
#pragma unroll
    for (int d = 0; d < 64; ++d) {
        v[d] = base[(size_t)d * N_PIX];
        m = fmaxf(m, v[d]);
    }
    float s = 0.f;
#pragma unroll
    for (int d = 0; d < 64; ++d) { v[d] = expf(v[d] - m); s += v[d]; }
    float inv = 0.125f / s;                        // scale = DHEAD^-0.5 = 1/8
#pragma unroll
    for (int d = 0; d < 64; ++d) base[(size_t)d * N_PIX] = v[d] * inv;
}

// ---------------- softmax over spatial dim N (16384) for k ----------------
// k rows: kv channels 0..511 per batch; one block per row.
__global__ void __launch_bounds__(256) k_softmax_k(float* __restrict__ kv)
{
    int row = blockIdx.x;                 // 0..4095
    int b = row >> 9, ch = row & 511;
    float* base = kv + ((size_t)b * 1024 + ch) * N_PIX;
    float4* b4 = (float4*)base;
    int t = threadIdx.x;
    int lane = t & 31, warp = t >> 5;

    __shared__ float red[40];

    float4 r[16];
    float m = -3.4e38f;
#pragma unroll
    for (int i = 0; i < 16; ++i) {
        r[i] = b4[t + i * 256];
        m = fmaxf(m, fmaxf(fmaxf(r[i].x, r[i].y), fmaxf(r[i].z, r[i].w)));
    }
#pragma unroll
    for (int o = 16; o; o >>= 1) m = fmaxf(m, __shfl_xor_sync(0xffffffffu, m, o));
    if (lane == 0) red[warp] = m;
    __syncthreads();
    if (t == 0) {
        float mm = red[0];
        for (int w = 1; w < 8; ++w) mm = fmaxf(mm, red[w]);
        red[32] = mm;
    }
    __syncthreads();
    m = red[32];

    float s = 0.f;
#pragma unroll
    for (int i = 0; i < 16; ++i) {
        r[i].x = expf(r[i].x - m);
        r[i].y = expf(r[i].y - m);
        r[i].z = expf(r[i].z - m);
        r[i].w = expf(r[i].w - m);
        s += r[i].x + r[i].y + r[i].z + r[i].w;
    }
#pragma unroll
    for (int o = 16; o; o >>= 1) s += __shfl_xor_sync(0xffffffffu, s, o);
    if (lane == 0) red[warp] = s;
    __syncthreads();
    if (t == 0) {
        float tt = 0.f;
        for (int w = 0; w < 8; ++w) tt += red[w];
        red[33] = tt;
    }
    __syncthreads();
    float inv = 1.0f / red[33];
#pragma unroll
    for (int i = 0; i < 16; ++i) {
        r[i].x *= inv; r[i].y *= inv; r[i].z *= inv; r[i].w *= inv;
        b4[t + i * 256] = r[i];
    }
}

// ---------------- context partials: P[bh][s][e][d] = sum_{n in slab s} v[e][n]*k[d][n] ----------------
__global__ void __launch_bounds__(256) k_ctx(const float* __restrict__ kv,
                                             float* __restrict__ part)
{
    __shared__ __align__(16) float ks[32][68];   // [nn][d], padded
    __shared__ __align__(16) float vs[32][68];

    int bh = blockIdx.x >> 3;
    int s  = blockIdx.x & 7;
    int b  = bh >> 3, h = bh & 7;
    const float* kb = kv + ((size_t)b * 1024 + (size_t)h * 64) * N_PIX;
    const float* vb = kv + ((size_t)b * 1024 + 512 + (size_t)h * 64) * N_PIX;

    int t  = threadIdx.x;
    int d0 = (t & 15) * 4;
    int e0 = (t >> 4) * 4;

    float acc[4][4];
#pragma unroll
    for (int j = 0; j < 4; ++j)
#pragma unroll
        for (int i = 0; i < 4; ++i) acc[j][i] = 0.f;

    int nbase = s * 2048;
    for (int nc = 0; nc < 2048; nc += 32) {
        int n0 = nbase + nc;
        __syncthreads();
#pragma unroll
        for (int rep = 0; rep < 2; ++rep) {
            int f   = t + rep * 256;
            int row = f >> 3;            // channel index 0..63
            int c4  = (f & 7) * 4;       // nn base
            float4 kk4 = *(const float4*)(kb + (size_t)row * N_PIX + n0 + c4);
            ks[c4 + 0][row] = kk4.x; ks[c4 + 1][row] = kk4.y;
            ks[c4 + 2][row] = kk4.z; ks[c4 + 3][row] = kk4.w;
            float4 vv4 = *(const float4*)(vb + (size_t)row * N_PIX + n0 + c4);
            vs[c4 + 0][row] = vv4.x; vs[c4 + 1][row] = vv4.y;
            vs[c4 + 2][row] = vv4.z; vs[c4 + 3][row] = vv4.w;
        }
        __syncthreads();
#pragma unroll
        for (int nn = 0; nn < 32; ++nn) {
            float4 kr = *(const float4*)&ks[nn][d0];
            float4 vr = *(const float4*)&vs[nn][e0];
            acc[0][0] += vr.x * kr.x; acc[0][1] += vr.x * kr.y; acc[0][2] += vr.x * kr.z; acc[0][3] += vr.x * kr.w;
            acc[1][0] += vr.y * kr.x; acc[1][1] += vr.y * kr.y; acc[1][2] += vr.y * kr.z; acc[1][3] += vr.y * kr.w;
            acc[2][0] += vr.z * kr.x; acc[2][1] += vr.z * kr.y; acc[2][2] += vr.z * kr.z; acc[2][3] += vr.z * kr.w;
            acc[3][0] += vr.w * kr.x; acc[3][1] += vr.w * kr.y; acc[3][2] += vr.w * kr.z; acc[3][3] += vr.w * kr.w;
        }
    }

    size_t obase = ((size_t)blockIdx.x * 64 + e0) * 64 + d0;
#pragma unroll
    for (int j = 0; j < 4; ++j) {
        float4 o4 = make_float4(acc[j][0], acc[j][1], acc[j][2], acc[j][3]);
        *(float4*)&part[obase + (size_t)j * 64] = o4;
    }
}

// ---------------- reduce context partials: ctx^T[bh][e][d] ----------------
__global__ void k_ctx_reduce(const float* __restrict__ part, float* __restrict__ ctx)
{
    int i  = blockIdx.x * 256 + threadIdx.x;   // < 262144
    int bh = i >> 12;
    int ed = i & 4095;
    float s = 0.f;
#pragma unroll
    for (int ss = 0; ss < 8; ++ss)
        s += part[((size_t)bh * 8 + ss) * 4096 + ed];
    ctx[i] = s;
}

// ---------------- launch ----------------
extern "C" void kernel_launch(void* const* d_in, const int* in_sizes, int n_in,
                              void* d_out, int out_size)
{
    const float* fmap  = (const float*)d_in[0];
    const float* w_q   = (const float*)d_in[1];
    const float* w_dw  = (const float*)d_in[2];
    const float* w_pw  = (const float*)d_in[3];
    const float* w_out = (const float*)d_in[4];
    const float* b_out = (const float*)d_in[5];
    float* out = (float*)d_out;

    float *dw, *q, *kvp, *av, *part, *ctx;
    cudaGetSymbolAddress((void**)&dw,   g_dw);
    cudaGetSymbolAddress((void**)&q,    g_q);
    cudaGetSymbolAddress((void**)&kvp,  g_kv);
    cudaGetSymbolAddress((void**)&av,   g_av);
    cudaGetSymbolAddress((void**)&part, g_part);
    cudaGetSymbolAddress((void**)&ctx,  g_ctx);

    // 1) depthwise 3x3
    k_dwconv<<<dim3(64, BATCH * CDIM), 256>>>(fmap, w_dw);

    // 2) q = w_q @ fmap        [b][512][N]
    k_gemm<128, false, false><<<dim3(128, 4, 8), 256>>>(
        fmap, w_q, nullptr, q, 256, N_PIX, 256LL * N_PIX, 0, 512LL * N_PIX);

    // 3) kv = w_pw @ dw        [b][1024][N]
    k_gemm<128, false, false><<<dim3(128, 8, 8), 256>>>(
        dw, w_pw, nullptr, kvp, 256, N_PIX, 256LL * N_PIX, 0, 1024LL * N_PIX);

    // 4) softmax over d for q (in place) * 1/8
    k_softmax_q<<<4096, 256>>>(q);

    // 5) softmax over N for k (in place, channels 0..511 of kv)
    k_softmax_k<<<4096, 256>>>(kvp);

    // 6) context split-K partials + reduce -> ctx^T[e][d] per (b,h)
    k_ctx<<<512, 256>>>(kvp, part);
    k_ctx_reduce<<<1024, 256>>>(part, ctx);

    // 7) av = gelu(ctx^T @ q)  batched over 64 (b,h) pairs   [b][512][N]
    k_gemm<64, true, false><<<dim3(128, 1, 64), 256>>>(
        q, ctx, nullptr, av, 64, N_PIX, 64LL * N_PIX, 4096LL, 64LL * N_PIX);

    // 8) out = w_out @ av + b_out   [b][256][N]
    k_gemm<128, false, true><<<dim3(128, 2, 8), 256>>>(
        av, w_out, b_out, out, 512, N_PIX, 512LL * N_PIX, 0, 256LL * N_PIX);
}

// round 3
// speedup vs baseline: 1.0017x; 1.0017x over previous
#include <cuda_runtime.h>
#include <math.h>

// ---------------- problem constants ----------------
#define N_PIX  16384          // 128*128 spatial
#define BATCH  8
#define CDIM   256
#define INNER  512            // HEADS*DIM_HEAD
#define NHEADS 8
#define DHEAD  64

// ---------------- scratch (static device globals; no allocation) ----------------
__device__ __align__(16) float g_dw  [(size_t)BATCH * CDIM  * N_PIX];   // depthwise conv out
__device__ __align__(16) float g_q   [(size_t)BATCH * INNER * N_PIX];   // q (then softmaxed)
__device__ __align__(16) float g_kv  [(size_t)BATCH * 2*INNER * N_PIX]; // k (ch 0..511), v (512..1023)
__device__ __align__(16) float g_av  [(size_t)BATCH * INNER * N_PIX];   // gelu(q@ctx)
__device__ __align__(16) float g_part[64 * 8 * 64 * 64];                // split-K context partials
__device__ __align__(16) float g_ctx [64 * 64 * 64];                    // per-(b,h) ctx^T  [e][d]

__device__ __forceinline__ float gelu_exact(float x) { return x * normcdff(x); }

// ---------------- depthwise 3x3, pad 1 ----------------
__global__ void __launch_bounds__(256) k_dwconv(const float* __restrict__ in,
                                                const float* __restrict__ wdw)
{
    int plane = blockIdx.y;              // b*256 + c
    int c     = plane & 255;
    const float* ip = in   + (size_t)plane * N_PIX;
    float*       op = g_dw + (size_t)plane * N_PIX;

    float w[9];
#pragma unroll
    for (int k = 0; k < 9; ++k) w[k] = __ldg(wdw + c * 9 + k);

    int p = blockIdx.x * 256 + threadIdx.x;      // 0..16383
    int y = p >> 7, x = p & 127;
    float s = 0.f;
#pragma unroll
    for (int dy = -1; dy <= 1; ++dy) {
        int yy = y + dy;
        if (yy < 0 || yy > 127) continue;
#pragma unroll
        for (int dx = -1; dx <= 1; ++dx) {
            int xx = x + dx;
            if (xx < 0 || xx > 127) continue;
            s += ip[yy * 128 + xx] * w[(dy + 1) * 3 + (dx + 1)];
        }
    }
    op[p] = s;
}

// ---------------- generic channel-major GEMM ----------------
// Y[o, p] = sum_c W[o, c] * X[c, p]     (X rows contiguous in p; W row-major [O, C])
// Batched over blockIdx.z with element strides xs/ws/ys. Optional GELU on output, bias add.
// Block: 128 pixels x BN outs, BK=8, 256 threads, per-thread 8 x (BN/16).
template <int BN, bool GELU_OUT, bool BIAS>
__global__ void __launch_bounds__(256) k_gemm(
    const float* __restrict__ X, const float* __restrict__ W,
    const float* __restrict__ bias, float* __restrict__ Y,
    int C, int N, long long xs, long long ws, long long ys)
{
    constexpr int BM = 128, BK = 8;
    constexpr int TN = BN / 16;          // 8 or 4

    __shared__ __align__(16) float Xs[BK][BM];
    __shared__ __align__(16) float Ws[BK][BN];

    const float* Xb = X + (long long)blockIdx.z * xs;
    const float* Wb = W + (long long)blockIdx.z * ws;
    float*       Yb = Y + (long long)blockIdx.z * ys;

    const int p0 = blockIdx.x * BM;
    const int o0 = blockIdx.y * BN;
    const int t  = threadIdx.x;
    const int tm = t & 15;               // pixel group
    const int tn = t >> 4;               // output group

    float acc[8][TN];
#pragma unroll
    for (int i = 0; i < 8; ++i)
#pragma unroll
        for (int j = 0; j < TN; ++j) acc[i][j] = 0.f;

    for (int c0 = 0; c0 < C; c0 += BK) {
        // --- load X tile: BK x BM  (exactly 256 float4) ---
        {
            int kk = t >> 5, p4 = t & 31;
            float4 xv = *(const float4*)(Xb + (size_t)(c0 + kk) * N + p0 + p4 * 4);
            *(float4*)&Xs[kk][p4 * 4] = xv;
        }
        // --- load W tile: BN x BK, transposed to Ws[k][o] ---
        for (int i = t; i < BN * BK / 4; i += 256) {
            int o = i >> 1, cq = i & 1;  // BK/4 == 2
            float4 wv = *(const float4*)(Wb + (size_t)(o0 + o) * C + c0 + cq * 4);
            Ws[cq * 4 + 0][o] = wv.x;
            Ws[cq * 4 + 1][o] = wv.y;
            Ws[cq * 4 + 2][o] = wv.z;
            Ws[cq * 4 + 3][o] = wv.w;
        }
        __syncthreads();

#pragma unroll
        for (int kk = 0; kk < BK; ++kk) {
            float a[8], b[TN];
#pragma unroll
            for (int cm = 0; cm < 2; ++cm) {
                float4 av = *(const float4*)&Xs[kk][tm * 4 + cm * 64];
                a[cm * 4 + 0] = av.x; a[cm * 4 + 1] = av.y;
                a[cm * 4 + 2] = av.z; a[cm * 4 + 3] = av.w;
            }
#pragma unroll
            for (int cn = 0; cn < TN / 4; ++cn) {
                float4 bv = *(const float4*)&Ws[kk][tn * 4 + cn * 64];
                b[cn * 4 + 0] = bv.x; b[cn * 4 + 1] = bv.y;
                b[cn * 4 + 2] = bv.z; b[cn * 4 + 3] = bv.w;
            }
#pragma unroll
            for (int i = 0; i < 8; ++i)
#pragma unroll
                for (int j = 0; j < TN; ++j)
                    acc[i][j] += a[i] * b[j];
        }
        __syncthreads();
    }

    // --- epilogue ---
#pragma unroll
    for (int cn = 0; cn < TN / 4; ++cn) {
#pragma unroll
        for (int j = 0; j < 4; ++j) {
            int o = o0 + tn * 4 + cn * 64 + j;
            float bb = 0.f;
            if (BIAS) bb = __ldg(&bias[o]);
#pragma unroll
            for (int cm = 0; cm < 2; ++cm) {
                float4 v;
                v.x = acc[cm * 4 + 0][cn * 4 + j] + bb;
                v.y = acc[cm * 4 + 1][cn * 4 + j] + bb;
                v.z = acc[cm * 4 + 2][cn * 4 + j] + bb;
                v.w = acc[cm * 4 + 3][cn * 4 + j] + bb;
                if (GELU_OUT) {
                    v.x = gelu_exact(v.x); v.y = gelu_exact(v.y);
                    v.z = gelu_exact(v.z); v.w = gelu_exact(v.w);
                }
                *(float4*)(Yb + (size_t)o * N + p0 + tm * 4 + cm * 64) = v;
            }
        }
    }
}

// ---------------- softmax over feature dim d (64) for q, then * scale ----------------
// q layout [B][512][N]; group = channels h*64 .. h*64+63 at fixed (b, n)
__global__ void __launch_bounds__(256) k_softmax_q(float* __restrict__ q)
{
    int idx = blockIdx.x * 256 + threadIdx.x;      // 8*8*16384 items
    int n   = idx & (N_PIX - 1);
    int bh  = idx >> 14;
    int b   = bh >> 3, h = bh & 7;
    float* base = q + ((size_t)b * INNER + (size_t)h * 64) * N_PIX + n;

    float v[64];
    float m = -3.4e38f;
#pragma unroll
    for (int d = 0; d < 64; ++d) {
        v[d] = base[(size_t)d * N_PIX];
        m = fmaxf(m, v[d]);
    }
    float s = 0.f;
#pragma unroll
    for (int d = 0; d < 64; ++d) { v[d] = expf(v[d] - m); s += v[d]; }
    float inv = 0.125f / s;                        // scale = DHEAD^-0.5 = 1/8
#pragma unroll
    for (int d = 0; d < 64; ++d) base[(size_t)d * N_PIX] = v[d] * inv;
}

// ---------------- softmax over spatial dim N (16384) for k ----------------
// k rows: kv channels 0..511 per batch; one block per row.
__global__ void __launch_bounds__(256) k_softmax_k(float* __restrict__ kv)
{
    int row = blockIdx.x;                 // 0..4095
    int b = row >> 9, ch = row & 511;
    float* base = kv + ((size_t)b * 1024 + ch) * N_PIX;
    float4* b4 = (float4*)base;
    int t = threadIdx.x;
    int lane = t & 31, warp = t >> 5;

    __shared__ float red[40];

    float4 r[16];
    float m = -3.4e38f;
#pragma unroll
    for (int i = 0; i < 16; ++i) {
        r[i] = b4[t + i * 256];
        m = fmaxf(m, fmaxf(fmaxf(r[i].x, r[i].y), fmaxf(r[i].z, r[i].w)));
    }
#pragma unroll
    for (int o = 16; o; o >>= 1) m = fmaxf(m, __shfl_xor_sync(0xffffffffu, m, o));
    if (lane == 0) red[warp] = m;
    __syncthreads();
    if (t == 0) {
        float mm = red[0];
        for (int w = 1; w < 8; ++w) mm = fmaxf(mm, red[w]);
        red[32] = mm;
    }
    __syncthreads();
    m = red[32];

    float s = 0.f;
#pragma unroll
    for (int i = 0; i < 16; ++i) {
        r[i].x = expf(r[i].x - m);
        r[i].y = expf(r[i].y - m);
        r[i].z = expf(r[i].z - m);
        r[i].w = expf(r[i].w - m);
        s += r[i].x + r[i].y + r[i].z + r[i].w;
    }
#pragma unroll
    for (int o = 16; o; o >>= 1) s += __shfl_xor_sync(0xffffffffu, s, o);
    if (lane == 0) red[warp] = s;
    __syncthreads();
    if (t == 0) {
        float tt = 0.f;
        for (int w = 0; w < 8; ++w) tt += red[w];
        red[33] = tt;
    }
    __syncthreads();
    float inv = 1.0f / red[33];
#pragma unroll
    for (int i = 0; i < 16; ++i) {
        r[i].x *= inv; r[i].y *= inv; r[i].z *= inv; r[i].w *= inv;
        b4[t + i * 256] = r[i];
    }
}

// ---------------- context partials: P[bh][s][e][d] = sum_{n in slab s} v[e][n]*k[d][n] ----------------
__global__ void __launch_bounds__(256) k_ctx(const float* __restrict__ kv,
                                             float* __restrict__ part)
{
    __shared__ __align__(16) float ks[32][68];   // [nn][d], padded
    __shared__ __align__(16) float vs[32][68];

    int bh = blockIdx.x >> 3;
    int s  = blockIdx.x & 7;
    int b  = bh >> 3, h = bh & 7;
    const float* kb = kv + ((size_t)b * 1024 + (size_t)h * 64) * N_PIX;
    const float* vb = kv + ((size_t)b * 1024 + 512 + (size_t)h * 64) * N_PIX;

    int t  = threadIdx.x;
    int d0 = (t & 15) * 4;
    int e0 = (t >> 4) * 4;

    float acc[4][4];
#pragma unroll
    for (int j = 0; j < 4; ++j)
#pragma unroll
        for (int i = 0; i < 4; ++i) acc[j][i] = 0.f;

    int nbase = s * 2048;
    for (int nc = 0; nc < 2048; nc += 32) {
        int n0 = nbase + nc;
        __syncthreads();
#pragma unroll
        for (int rep = 0; rep < 2; ++rep) {
            int f   = t + rep * 256;
            int row = f >> 3;            // channel index 0..63
            int c4  = (f & 7) * 4;       // nn base
            float4 kk4 = *(const float4*)(kb + (size_t)row * N_PIX + n0 + c4);
            ks[c4 + 0][row] = kk4.x; ks[c4 + 1][row] = kk4.y;
            ks[c4 + 2][row] = kk4.z; ks[c4 + 3][row] = kk4.w;
            float4 vv4 = *(const float4*)(vb + (size_t)row * N_PIX + n0 + c4);
            vs[c4 + 0][row] = vv4.x; vs[c4 + 1][row] = vv4.y;
            vs[c4 + 2][row] = vv4.z; vs[c4 + 3][row] = vv4.w;
        }
        __syncthreads();
#pragma unroll
        for (int nn = 0; nn < 32; ++nn) {
            float4 kr = *(const float4*)&ks[nn][d0];
            float4 vr = *(const float4*)&vs[nn][e0];
            acc[0][0] += vr.x * kr.x; acc[0][1] += vr.x * kr.y; acc[0][2] += vr.x * kr.z; acc[0][3] += vr.x * kr.w;
            acc[1][0] += vr.y * kr.x; acc[1][1] += vr.y * kr.y; acc[1][2] += vr.y * kr.z; acc[1][3] += vr.y * kr.w;
            acc[2][0] += vr.z * kr.x; acc[2][1] += vr.z * kr.y; acc[2][2] += vr.z * kr.z; acc[2][3] += vr.z * kr.w;
            acc[3][0] += vr.w * kr.x; acc[3][1] += vr.w * kr.y; acc[3][2] += vr.w * kr.z; acc[3][3] += vr.w * kr.w;
        }
    }

    size_t obase = ((size_t)blockIdx.x * 64 + e0) * 64 + d0;
#pragma unroll
    for (int j = 0; j < 4; ++j) {
        float4 o4 = make_float4(acc[j][0], acc[j][1], acc[j][2], acc[j][3]);
        *(float4*)&part[obase + (size_t)j * 64] = o4;
    }
}

// ---------------- reduce context partials: ctx^T[bh][e][d] ----------------
__global__ void k_ctx_reduce(const float* __restrict__ part, float* __restrict__ ctx)
{
    int i  = blockIdx.x * 256 + threadIdx.x;   // < 262144
    int bh = i >> 12;
    int ed = i & 4095;
    float s = 0.f;
#pragma unroll
    for (int ss = 0; ss < 8; ++ss)
        s += part[((size_t)bh * 8 + ss) * 4096 + ed];
    ctx[i] = s;
}

// ---------------- launch ----------------
extern "C" void kernel_launch(void* const* d_in, const int* in_sizes, int n_in,
                              void* d_out, int out_size)
{
    const float* fmap  = (const float*)d_in[0];
    const float* w_q   = (const float*)d_in[1];
    const float* w_dw  = (const float*)d_in[2];
    const float* w_pw  = (const float*)d_in[3];
    const float* w_out = (const float*)d_in[4];
    const float* b_out = (const float*)d_in[5];
    float* out = (float*)d_out;

    float *dw, *q, *kvp, *av, *part, *ctx;
    cudaGetSymbolAddress((void**)&dw,   g_dw);
    cudaGetSymbolAddress((void**)&q,    g_q);
    cudaGetSymbolAddress((void**)&kvp,  g_kv);
    cudaGetSymbolAddress((void**)&av,   g_av);
    cudaGetSymbolAddress((void**)&part, g_part);
    cudaGetSymbolAddress((void**)&ctx,  g_ctx);

    // 1) depthwise 3x3
    k_dwconv<<<dim3(64, BATCH * CDIM), 256>>>(fmap, w_dw);

    // 2) q = w_q @ fmap        [b][512][N]
    k_gemm<128, false, false><<<dim3(128, 4, 8), 256>>>(
        fmap, w_q, nullptr, q, 256, N_PIX, 256LL * N_PIX, 0, 512LL * N_PIX);

    // 3) kv = w_pw @ dw        [b][1024][N]
    k_gemm<128, false, false><<<dim3(128, 8, 8), 256>>>(
        dw, w_pw, nullptr, kvp, 256, N_PIX, 256LL * N_PIX, 0, 1024LL * N_PIX);

    // 4) softmax over d for q (in place) * 1/8
    k_softmax_q<<<4096, 256>>>(q);

    // 5) softmax over N for k (in place, channels 0..511 of kv)
    k_softmax_k<<<4096, 256>>>(kvp);

    // 6) context split-K partials + reduce -> ctx^T[e][d] per (b,h)
    k_ctx<<<512, 256>>>(kvp, part);
    k_ctx_reduce<<<1024, 256>>>(part, ctx);

    // 7) av = gelu(ctx^T @ q)  batched over 64 (b,h) pairs   [b][512][N]
    k_gemm<64, true, false><<<dim3(128, 1, 64), 256>>>(
        q, ctx, nullptr, av, 64, N_PIX, 64LL * N_PIX, 4096LL, 64LL * N_PIX);

    // 8) out = w_out @ av + b_out   [b][256][N]
    k_gemm<128, false, true><<<dim3(128, 2, 8), 256>>>(
        av, w_out, b_out, out, 512, N_PIX, 512LL * N_PIX, 0, 256LL * N_PIX);
}

// round 4
// speedup vs baseline: 1.0032x; 1.0015x over previous
#include <cuda_runtime.h>
#include <math.h>

// ---------------- problem constants ----------------
#define N_PIX  16384          // 128*128 spatial
#define BATCH  8
#define CDIM   256
#define INNER  512            // HEADS*DIM_HEAD
#define NHEADS 8
#define DHEAD  64

// ---------------- scratch (static device globals; no allocation) ----------------
__device__ __align__(16) float g_dw  [(size_t)BATCH * CDIM  * N_PIX];   // depthwise conv out
__device__ __align__(16) float g_q   [(size_t)BATCH * INNER * N_PIX];   // q (then softmaxed)
__device__ __align__(16) float g_kv  [(size_t)BATCH * 2*INNER * N_PIX]; // k (ch 0..511), v (512..1023)
__device__ __align__(16) float g_av  [(size_t)BATCH * INNER * N_PIX];   // gelu(q@ctx)
__device__ __align__(16) float g_part[64 * 8 * 64 * 64];                // split-K context partials
__device__ __align__(16) float g_ctx [64 * 64 * 64];                    // per-(b,h) ctx^T  [e][d]

__device__ __forceinline__ float gelu_exact(float x) { return x * normcdff(x); }

// ---------------- depthwise 3x3, pad 1 ----------------
__global__ void __launch_bounds__(256) k_dwconv(const float* __restrict__ in,
                                                const float* __restrict__ wdw)
{
    int plane = blockIdx.y;              // b*256 + c
    int c     = plane & 255;
    const float* ip = in   + (size_t)plane * N_PIX;
    float*       op = g_dw + (size_t)plane * N_PIX;

    float w[9];
#pragma unroll
    for (int k = 0; k < 9; ++k) w[k] = __ldg(wdw + c * 9 + k);

    int p = blockIdx.x * 256 + threadIdx.x;      // 0..16383
    int y = p >> 7, x = p & 127;
    float s = 0.f;
#pragma unroll
    for (int dy = -1; dy <= 1; ++dy) {
        int yy = y + dy;
        if (yy < 0 || yy > 127) continue;
#pragma unroll
        for (int dx = -1; dx <= 1; ++dx) {
            int xx = x + dx;
            if (xx < 0 || xx > 127) continue;
            s += ip[yy * 128 + xx] * w[(dy + 1) * 3 + (dx + 1)];
        }
    }
    op[p] = s;
}

// ---------------- generic channel-major GEMM ----------------
// Y[o, p] = sum_c W[o, c] * X[c, p]     (X rows contiguous in p; W row-major [O, C])
// Batched over blockIdx.z with element strides xs/ws/ys. Optional GELU on output, bias add.
// Block: 128 pixels x BN outs, BK=8, 256 threads, per-thread 8 x (BN/16).
template <int BN, bool GELU_OUT, bool BIAS>
__global__ void __launch_bounds__(256) k_gemm(
    const float* __restrict__ X, const float* __restrict__ W,
    const float* __restrict__ bias, float* __restrict__ Y,
    int C, int N, long long xs, long long ws, long long ys)
{
    constexpr int BM = 128, BK = 8;
    constexpr int TN = BN / 16;          // 8 or 4

    __shared__ __align__(16) float Xs[BK][BM];
    __shared__ __align__(16) float Ws[BK][BN];

    const float* Xb = X + (long long)blockIdx.z * xs;
    const float* Wb = W + (long long)blockIdx.z * ws;
    float*       Yb = Y + (long long)blockIdx.z * ys;

    const int p0 = blockIdx.x * BM;
    const int o0 = blockIdx.y * BN;
    const int t  = threadIdx.x;
    const int tm = t & 15;               // pixel group
    const int tn = t >> 4;               // output group

    float acc[8][TN];
#pragma unroll
    for (int i = 0; i < 8; ++i)
#pragma unroll
        for (int j = 0; j < TN; ++j) acc[i][j] = 0.f;

    for (int c0 = 0; c0 < C; c0 += BK) {
        // --- load X tile: BK x BM  (exactly 256 float4) ---
        {
            int kk = t >> 5, p4 = t & 31;
            float4 xv = *(const float4*)(Xb + (size_t)(c0 + kk) * N + p0 + p4 * 4);
            *(float4*)&Xs[kk][p4 * 4] = xv;
        }
        // --- load W tile: BN x BK, transposed to Ws[k][o] ---
        for (int i = t; i < BN * BK / 4; i += 256) {
            int o = i >> 1, cq = i & 1;  // BK/4 == 2
            float4 wv = *(const float4*)(Wb + (size_t)(o0 + o) * C + c0 + cq * 4);
            Ws[cq * 4 + 0][o] = wv.x;
            Ws[cq * 4 + 1][o] = wv.y;
            Ws[cq * 4 + 2][o] = wv.z;
            Ws[cq * 4 + 3][o] = wv.w;
        }
        __syncthreads();

#pragma unroll
        for (int kk = 0; kk < BK; ++kk) {
            float a[8], b[TN];
#pragma unroll
            for (int cm = 0; cm < 2; ++cm) {
                float4 av = *(const float4*)&Xs[kk][tm * 4 + cm * 64];
                a[cm * 4 + 0] = av.x; a[cm * 4 + 1] = av.y;
                a[cm * 4 + 2] = av.z; a[cm * 4 + 3] = av.w;
            }
#pragma unroll
            for (int cn = 0; cn < TN / 4; ++cn) {
                float4 bv = *(const float4*)&Ws[kk][tn * 4 + cn * 64];
                b[cn * 4 + 0] = bv.x; b[cn * 4 + 1] = bv.y;
                b[cn * 4 + 2] = bv.z; b[cn * 4 + 3] = bv.w;
            }
#pragma unroll
            for (int i = 0; i < 8; ++i)
#pragma unroll
                for (int j = 0; j < TN; ++j)
                    acc[i][j] += a[i] * b[j];
        }
        __syncthreads();
    }

    // --- epilogue ---
#pragma unroll
    for (int cn = 0; cn < TN / 4; ++cn) {
#pragma unroll
        for (int j = 0; j < 4; ++j) {
            int o = o0 + tn * 4 + cn * 64 + j;
            float bb = 0.f;
            if (BIAS) bb = __ldg(&bias[o]);
#pragma unroll
            for (int cm = 0; cm < 2; ++cm) {
                float4 v;
                v.x = acc[cm * 4 + 0][cn * 4 + j] + bb;
                v.y = acc[cm * 4 + 1][cn * 4 + j] + bb;
                v.z = acc[cm * 4 + 2][cn * 4 + j] + bb;
                v.w = acc[cm * 4 + 3][cn * 4 + j] + bb;
                if (GELU_OUT) {
                    v.x = gelu_exact(v.x); v.y = gelu_exact(v.y);
                    v.z = gelu_exact(v.z); v.w = gelu_exact(v.w);
                }
                *(float4*)(Yb + (size_t)o * N + p0 + tm * 4 + cm * 64) = v;
            }
        }
    }
}

// ---------------- softmax over feature dim d (64) for q, then * scale ----------------
// q layout [B][512][N]; group = channels h*64 .. h*64+63 at fixed (b, n)
__global__ void __launch_bounds__(256) k_softmax_q(float* __restrict__ q)
{
    int idx = blockIdx.x * 256 + threadIdx.x;      // 8*8*16384 items
    int n   = idx & (N_PIX - 1);
    int bh  = idx >> 14;
    int b   = bh >> 3, h = bh & 7;
    float* base = q + ((size_t)b * INNER + (size_t)h * 64) * N_PIX + n;

    float v[64];
    float m = -3.4e38f;
#pragma unroll
    for (int d = 0; d < 64; ++d) {
        v[d] = base[(size_t)d * N_PIX];
        m = fmaxf(m, v[d]);
    }
    float s = 0.f;
#pragma unroll
    for (int d = 0; d < 64; ++d) { v[d] = expf(v[d] - m); s += v[d]; }
    float inv = 0.125f / s;                        // scale = DHEAD^-0.5 = 1/8
#pragma unroll
    for (int d = 0; d < 64; ++d) base[(size_t)d * N_PIX] = v[d] * inv;
}

// ---------------- softmax over spatial dim N (16384) for k ----------------
// k rows: kv channels 0..511 per batch; one block per row.
__global__ void __launch_bounds__(256) k_softmax_k(float* __restrict__ kv)
{
    int row = blockIdx.x;                 // 0..4095
    int b = row >> 9, ch = row & 511;
    float* base = kv + ((size_t)b * 1024 + ch) * N_PIX;
    float4* b4 = (float4*)base;
    int t = threadIdx.x;
    int lane = t & 31, warp = t >> 5;

    __shared__ float red[40];

    float4 r[16];
    float m = -3.4e38f;
#pragma unroll
    for (int i = 0; i < 16; ++i) {
        r[i] = b4[t + i * 256];
        m = fmaxf(m, fmaxf(fmaxf(r[i].x, r[i].y), fmaxf(r[i].z, r[i].w)));
    }
#pragma unroll
    for (int o = 16; o; o >>= 1) m = fmaxf(m, __shfl_xor_sync(0xffffffffu, m, o));
    if (lane == 0) red[warp] = m;
    __syncthreads();
    if (t == 0) {
        float mm = red[0];
        for (int w = 1; w < 8; ++w) mm = fmaxf(mm, red[w]);
        red[32] = mm;
    }
    __syncthreads();
    m = red[32];

    float s = 0.f;
#pragma unroll
    for (int i = 0; i < 16; ++i) {
        r[i].x = expf(r[i].x - m);
        r[i].y = expf(r[i].y - m);
        r[i].z = expf(r[i].z - m);
        r[i].w = expf(r[i].w - m);
        s += r[i].x + r[i].y + r[i].z + r[i].w;
    }
#pragma unroll
    for (int o = 16; o; o >>= 1) s += __shfl_xor_sync(0xffffffffu, s, o);
    if (lane == 0) red[warp] = s;
    __syncthreads();
    if (t == 0) {
        float tt = 0.f;
        for (int w = 0; w < 8; ++w) tt += red[w];
        red[33] = tt;
    }
    __syncthreads();
    float inv = 1.0f / red[33];
#pragma unroll
    for (int i = 0; i < 16; ++i) {
        r[i].x *= inv; r[i].y *= inv; r[i].z *= inv; r[i].w *= inv;
        b4[t + i * 256] = r[i];
    }
}

// ---------------- context partials: P[bh][s][e][d] = sum_{n in slab s} v[e][n]*k[d][n] ----------------
__global__ void __launch_bounds__(256) k_ctx(const float* __restrict__ kv,
                                             float* __restrict__ part)
{
    __shared__ __align__(16) float ks[32][68];   // [nn][d], padded
    __shared__ __align__(16) float vs[32][68];

    int bh = blockIdx.x >> 3;
    int s  = blockIdx.x & 7;
    int b  = bh >> 3, h = bh & 7;
    const float* kb = kv + ((size_t)b * 1024 + (size_t)h * 64) * N_PIX;
    const float* vb = kv + ((size_t)b * 1024 + 512 + (size_t)h * 64) * N_PIX;

    int t  = threadIdx.x;
    int d0 = (t & 15) * 4;
    int e0 = (t >> 4) * 4;

    float acc[4][4];
#pragma unroll
    for (int j = 0; j < 4; ++j)
#pragma unroll
        for (int i = 0; i < 4; ++i) acc[j][i] = 0.f;

    int nbase = s * 2048;
    for (int nc = 0; nc < 2048; nc += 32) {
        int n0 = nbase + nc;
        __syncthreads();
#pragma unroll
        for (int rep = 0; rep < 2; ++rep) {
            int f   = t + rep * 256;
            int row = f >> 3;            // channel index 0..63
            int c4  = (f & 7) * 4;       // nn base
            float4 kk4 = *(const float4*)(kb + (size_t)row * N_PIX + n0 + c4);
            ks[c4 + 0][row] = kk4.x; ks[c4 + 1][row] = kk4.y;
            ks[c4 + 2][row] = kk4.z; ks[c4 + 3][row] = kk4.w;
            float4 vv4 = *(const float4*)(vb + (size_t)row * N_PIX + n0 + c4);
            vs[c4 + 0][row] = vv4.x; vs[c4 + 1][row] = vv4.y;
            vs[c4 + 2][row] = vv4.z; vs[c4 + 3][row] = vv4.w;
        }
        __syncthreads();
#pragma unroll
        for (int nn = 0; nn < 32; ++nn) {
            float4 kr = *(const float4*)&ks[nn][d0];
            float4 vr = *(const float4*)&vs[nn][e0];
            acc[0][0] += vr.x * kr.x; acc[0][1] += vr.x * kr.y; acc[0][2] += vr.x * kr.z; acc[0][3] += vr.x * kr.w;
            acc[1][0] += vr.y * kr.x; acc[1][1] += vr.y * kr.y; acc[1][2] += vr.y * kr.z; acc[1][3] += vr.y * kr.w;
            acc[2][0] += vr.z * kr.x; acc[2][1] += vr.z * kr.y; acc[2][2] += vr.z * kr.z; acc[2][3] += vr.z * kr.w;
            acc[3][0] += vr.w * kr.x; acc[3][1] += vr.w * kr.y; acc[3][2] += vr.w * kr.z; acc[3][3] += vr.w * kr.w;
        }
    }

    size_t obase = ((size_t)blockIdx.x * 64 + e0) * 64 + d0;
#pragma unroll
    for (int j = 0; j < 4; ++j) {
        float4 o4 = make_float4(acc[j][0], acc[j][1], acc[j][2], acc[j][3]);
        *(float4*)&part[obase + (size_t)j * 64] = o4;
    }
}

// ---------------- reduce context partials: ctx^T[bh][e][d] ----------------
__global__ void k_ctx_reduce(const float* __restrict__ part, float* __restrict__ ctx)
{
    int i  = blockIdx.x * 256 + threadIdx.x;   // < 262144
    int bh = i >> 12;
    int ed = i & 4095;
    float s = 0.f;
#pragma unroll
    for (int ss = 0; ss < 8; ++ss)
        s += part[((size_t)bh * 8 + ss) * 4096 + ed];
    ctx[i] = s;
}

// ---------------- launch ----------------
extern "C" void kernel_launch(void* const* d_in, const int* in_sizes, int n_in,
                              void* d_out, int out_size)
{
    const float* fmap  = (const float*)d_in[0];
    const float* w_q   = (const float*)d_in[1];
    const float* w_dw  = (const float*)d_in[2];
    const float* w_pw  = (const float*)d_in[3];
    const float* w_out = (const float*)d_in[4];
    const float* b_out = (const float*)d_in[5];
    float* out = (float*)d_out;

    float *dw, *q, *kvp, *av, *part, *ctx;
    cudaGetSymbolAddress((void**)&dw,   g_dw);
    cudaGetSymbolAddress((void**)&q,    g_q);
    cudaGetSymbolAddress((void**)&kvp,  g_kv);
    cudaGetSymbolAddress((void**)&av,   g_av);
    cudaGetSymbolAddress((void**)&part, g_part);
    cudaGetSymbolAddress((void**)&ctx,  g_ctx);

    // 1) depthwise 3x3
    k_dwconv<<<dim3(64, BATCH * CDIM), 256>>>(fmap, w_dw);

    // 2) q = w_q @ fmap        [b][512][N]
    k_gemm<128, false, false><<<dim3(128, 4, 8), 256>>>(
        fmap, w_q, nullptr, q, 256, N_PIX, 256LL * N_PIX, 0, 512LL * N_PIX);

    // 3) kv = w_pw @ dw        [b][1024][N]
    k_gemm<128, false, false><<<dim3(128, 8, 8), 256>>>(
        dw, w_pw, nullptr, kvp, 256, N_PIX, 256LL * N_PIX, 0, 1024LL * N_PIX);

    // 4) softmax over d for q (in place) * 1/8
    k_softmax_q<<<4096, 256>>>(q);

    // 5) softmax over N for k (in place, channels 0..511 of kv)
    k_softmax_k<<<4096, 256>>>(kvp);

    // 6) context split-K partials + reduce -> ctx^T[e][d] per (b,h)
    k_ctx<<<512, 256>>>(kvp, part);
    k_ctx_reduce<<<1024, 256>>>(part, ctx);

    // 7) av = gelu(ctx^T @ q)  batched over 64 (b,h) pairs   [b][512][N]
    k_gemm<64, true, false><<<dim3(128, 1, 64), 256>>>(
        q, ctx, nullptr, av, 64, N_PIX, 64LL * N_PIX, 4096LL, 64LL * N_PIX);

    // 8) out = w_out @ av + b_out   [b][256][N]
    k_gemm<128, false, true><<<dim3(128, 2, 8), 256>>>(
        av, w_out, b_out, out, 512, N_PIX, 512LL * N_PIX, 0, 256LL * N_PIX);
}

// round 5
// speedup vs baseline: 1.8899x; 1.8838x over previous
#include <cuda_runtime.h>
#include <cuda_bf16.h>
#include <math.h>
#include <stdint.h>

#define N_PIX  16384
#define BATCH  8

typedef __nv_bfloat16 bf16;

// ---------------- scratch (static device globals; no allocation) ----------------
__device__ __align__(16) float g_q   [(size_t)BATCH * 512 * N_PIX];   // q fp32 pre-softmax
__device__ __align__(16) float g_k   [(size_t)BATCH * 512 * N_PIX];   // k fp32 pre-softmax
__device__ __align__(16) float g_part[64 * 8 * 64 * 64];

__device__ __align__(16) bf16 g_fhi [(size_t)BATCH * 256 * N_PIX];
__device__ __align__(16) bf16 g_flo [(size_t)BATCH * 256 * N_PIX];
__device__ __align__(16) bf16 g_dwhi[(size_t)BATCH * 256 * N_PIX];
__device__ __align__(16) bf16 g_dwlo[(size_t)BATCH * 256 * N_PIX];
__device__ __align__(16) bf16 g_qhi [(size_t)BATCH * 512 * N_PIX];
__device__ __align__(16) bf16 g_qlo [(size_t)BATCH * 512 * N_PIX];
__device__ __align__(16) bf16 g_khi [(size_t)BATCH * 512 * N_PIX];
__device__ __align__(16) bf16 g_klo [(size_t)BATCH * 512 * N_PIX];
__device__ __align__(16) bf16 g_vhi [(size_t)BATCH * 512 * N_PIX];
__device__ __align__(16) bf16 g_vlo [(size_t)BATCH * 512 * N_PIX];
__device__ __align__(16) bf16 g_avhi[(size_t)BATCH * 512 * N_PIX];
__device__ __align__(16) bf16 g_avlo[(size_t)BATCH * 512 * N_PIX];
__device__ __align__(16) bf16 g_ctxhi[64 * 64 * 64];
__device__ __align__(16) bf16 g_ctxlo[64 * 64 * 64];
__device__ __align__(16) bf16 g_wqhi [512 * 256],  g_wqlo [512 * 256];
__device__ __align__(16) bf16 g_wpwhi[1024 * 256], g_wpwlo[1024 * 256];
__device__ __align__(16) bf16 g_wohi [256 * 512],  g_wolo [256 * 512];

// ---------------- helpers ----------------
__device__ __forceinline__ float gelu_exact(float x) { return x * normcdff(x); }
__device__ __forceinline__ void fsplit(float x, bf16& h, bf16& l) {
    h = __float2bfloat16_rn(x);
    l = __float2bfloat16_rn(x - __bfloat162float(h));
}
__device__ __forceinline__ uint32_t pack2(bf16 a, bf16 b) {
    __nv_bfloat162 t; t.x = a; t.y = b;
    return *reinterpret_cast<uint32_t*>(&t);
}
__device__ __forceinline__ void mma_bf16(float d[4], const uint32_t a[4], const uint32_t b[2]) {
    asm volatile("mma.sync.aligned.m16n8k16.row.col.f32.bf16.bf16.f32 "
                 "{%0,%1,%2,%3}, {%4,%5,%6,%7}, {%8,%9}, {%0,%1,%2,%3};"
                 : "+f"(d[0]), "+f"(d[1]), "+f"(d[2]), "+f"(d[3])
                 : "r"(a[0]), "r"(a[1]), "r"(a[2]), "r"(a[3]), "r"(b[0]), "r"(b[1]));
}
__device__ __forceinline__ void ldsm4(uint32_t r[4], uint32_t addr) {
    asm volatile("ldmatrix.sync.aligned.m8n8.x4.shared.b16 {%0,%1,%2,%3}, [%4];"
                 : "=r"(r[0]), "=r"(r[1]), "=r"(r[2]), "=r"(r[3]) : "r"(addr));
}
__device__ __forceinline__ void ldsm4t(uint32_t r[4], uint32_t addr) {
    asm volatile("ldmatrix.sync.aligned.m8n8.x4.trans.shared.b16 {%0,%1,%2,%3}, [%4];"
                 : "=r"(r[0]), "=r"(r[1]), "=r"(r[2]), "=r"(r[3]) : "r"(addr));
}
__device__ __forceinline__ uint32_t s2u(const void* p) {
    return (uint32_t)__cvta_generic_to_shared(p);
}

// ---------------- weight convert: fp32 -> bf16 hi/lo ----------------
__global__ void k_cvt(const float* __restrict__ x, bf16* __restrict__ hi,
                      bf16* __restrict__ lo, int n)
{
    int i = blockIdx.x * 256 + threadIdx.x;
    if (i < n) { bf16 h, l; fsplit(x[i], h, l); hi[i] = h; lo[i] = l; }
}

// ---------------- depthwise 3x3 (pad 1); emit dw and fmap hi/lo planes ----------------
__global__ void __launch_bounds__(256) k_dwconv(const float* __restrict__ in,
                                                const float* __restrict__ wdw)
{
    int plane = blockIdx.y;              // b*256 + c
    int c = plane & 255;
    const float* ip = in + (size_t)plane * N_PIX;

    float w[9];
#pragma unroll
    for (int k = 0; k < 9; ++k) w[k] = __ldg(wdw + c * 9 + k);

    int p = blockIdx.x * 256 + threadIdx.x;
    int y = p >> 7, x = p & 127;
    float s = 0.f;
#pragma unroll
    for (int dy = -1; dy <= 1; ++dy) {
        int yy = y + dy;
        if (yy < 0 || yy > 127) continue;
#pragma unroll
        for (int dx = -1; dx <= 1; ++dx) {
            int xx = x + dx;
            if (xx < 0 || xx > 127) continue;
            s += ip[yy * 128 + xx] * w[(dy + 1) * 3 + (dx + 1)];
        }
    }
    size_t o = (size_t)plane * N_PIX + p;
    bf16 h, l;
    fsplit(s, h, l);     g_dwhi[o] = h; g_dwlo[o] = l;
    fsplit(ip[p], h, l); g_fhi[o]  = h; g_flo[o]  = l;
}

// ---------------- split-bf16 tensor-core GEMM: Y[o,p] = sum_c A[o,c] * X[c,p] ----------------
// A hi/lo row-major [O,C]; X hi/lo [C, N_PIX] (p-contiguous). Batched via blockIdx.z.
// MODE: 0 = fp32 out, 1 = hi/lo out, 2 = gelu + hi/lo out, 3 = bias + fp32 out.
template <int BM, int MODE>
__global__ void __launch_bounds__(256, 2) k_mma_gemm(
    const bf16* __restrict__ Ahi, const bf16* __restrict__ Alo,
    const bf16* __restrict__ Bhi, const bf16* __restrict__ Blo,
    const float* __restrict__ bias,
    float* __restrict__ Yf, bf16* __restrict__ Yhi, bf16* __restrict__ Ylo,
    int C, long long as_, long long xs, long long ys)
{
    constexpr int BN = 128, BK = 32, AP = 40, BP = 136;
    constexpr int WM = BM / 2, MT = WM / 16;

    __shared__ bf16 Ash[2][BM * AP];
    __shared__ bf16 Bsh[2][BK * BP];

    const int t = threadIdx.x, warp = t >> 5, lane = t & 31;
    const int wm = warp & 1, wn = warp >> 1;           // 2 x 4 warp grid
    const int g = lane >> 2, tig = lane & 3;
    const int pblk = blockIdx.x * BN, o0 = blockIdx.y * BM;
    const long long z = blockIdx.z;
    const bf16* AH = Ahi + z * as_;
    const bf16* AL = Alo + z * as_;
    const bf16* XH = Bhi + z * xs;
    const bf16* XL = Blo + z * xs;

    const uint32_t aB0 = s2u(&Ash[0][0]), aB1 = s2u(&Ash[1][0]);
    const uint32_t bB0 = s2u(&Bsh[0][0]), bB1 = s2u(&Bsh[1][0]);

    float acc[MT][4][4];
#pragma unroll
    for (int m = 0; m < MT; ++m)
#pragma unroll
        for (int n = 0; n < 4; ++n)
#pragma unroll
            for (int r = 0; r < 4; ++r) acc[m][n][r] = 0.f;

    const int l15 = lane & 15;           // ldmatrix row-in-tile
    const int hi8 = (lane >> 4) * 8;     // ldmatrix col-half select

    for (int c0 = 0; c0 < C; c0 += BK) {
        __syncthreads();
#pragma unroll
        for (int i = t; i < BM * 4; i += 256) {          // A: BM x 32, both planes
            int m = i >> 2, kq = (i & 3) * 8;
            size_t src = (size_t)(o0 + m) * C + c0 + kq;
            *(uint4*)&Ash[0][m * AP + kq] = *(const uint4*)(AH + src);
            *(uint4*)&Ash[1][m * AP + kq] = *(const uint4*)(AL + src);
        }
#pragma unroll
        for (int i = t; i < 512; i += 256) {             // B: 32 x 128, both planes
            int c = i >> 4, pq = (i & 15) * 8;
            size_t src = (size_t)(c0 + c) * N_PIX + pblk + pq;
            *(uint4*)&Bsh[0][c * BP + pq] = *(const uint4*)(XH + src);
            *(uint4*)&Bsh[1][c * BP + pq] = *(const uint4*)(XL + src);
        }
        __syncthreads();

#pragma unroll
        for (int ks = 0; ks < BK; ks += 16) {
            uint32_t bh_[4][2], bl_[4][2], r[4];
#pragma unroll
            for (int nn = 0; nn < 2; ++nn) {             // 2 x (x4.trans) per plane
                uint32_t off = (uint32_t)((ks + l15) * BP + wn * 32 + nn * 16 + hi8) * 2;
                ldsm4t(r, bB0 + off);
                bh_[nn*2][0] = r[0]; bh_[nn*2][1] = r[1];
                bh_[nn*2+1][0] = r[2]; bh_[nn*2+1][1] = r[3];
                ldsm4t(r, bB1 + off);
                bl_[nn*2][0] = r[0]; bl_[nn*2][1] = r[1];
                bl_[nn*2+1][0] = r[2]; bl_[nn*2+1][1] = r[3];
            }
#pragma unroll
            for (int mt = 0; mt < MT; ++mt) {
                uint32_t ah[4], al[4];
                uint32_t off = (uint32_t)((wm * WM + mt * 16 + l15) * AP + ks + hi8) * 2;
                ldsm4(ah, aB0 + off);
                ldsm4(al, aB1 + off);
#pragma unroll
                for (int nt = 0; nt < 4; ++nt) {
                    mma_bf16(acc[mt][nt], ah, bh_[nt]);
                    mma_bf16(acc[mt][nt], al, bh_[nt]);
                    mma_bf16(acc[mt][nt], ah, bl_[nt]);
                }
            }
        }
    }

    // epilogue: c0=C[g][tig*2], c1=C[g][tig*2+1], c2=C[g+8][tig*2], c3=C[g+8][tig*2+1]
#pragma unroll
    for (int mt = 0; mt < MT; ++mt) {
#pragma unroll
        for (int h2 = 0; h2 < 2; ++h2) {
            int rrow = o0 + wm * WM + mt * 16 + g + h2 * 8;
            float bb = (MODE == 3) ? __ldg(&bias[rrow]) : 0.f;
#pragma unroll
            for (int nt = 0; nt < 4; ++nt) {
                int p = pblk + wn * 32 + nt * 8 + tig * 2;
                float v0 = acc[mt][nt][h2 * 2 + 0] + bb;
                float v1 = acc[mt][nt][h2 * 2 + 1] + bb;
                size_t o = (size_t)rrow * N_PIX + p;
                if (MODE == 0 || MODE == 3) {
                    *(float2*)(Yf + z * ys + o) = make_float2(v0, v1);
                } else {
                    if (MODE == 2) { v0 = gelu_exact(v0); v1 = gelu_exact(v1); }
                    bf16 h0, l0, h1, l1;
                    fsplit(v0, h0, l0); fsplit(v1, h1, l1);
                    *(uint32_t*)(Yhi + z * ys + o) = pack2(h0, h1);
                    *(uint32_t*)(Ylo + z * ys + o) = pack2(l0, l1);
                }
            }
        }
    }
}

// ---------------- softmax over feature dim (64) for q; scale 1/8; emit hi/lo ----------------
__global__ void __launch_bounds__(256) k_softmax_q(const float* __restrict__ q,
                                                   bf16* __restrict__ qhi, bf16* __restrict__ qlo)
{
    int idx = blockIdx.x * 256 + threadIdx.x;
    int n = idx & (N_PIX - 1);
    int bh = idx >> 14;
    size_t base = (size_t)bh * 64 * N_PIX + n;

    float v[64];
    float m = -3.4e38f;
#pragma unroll
    for (int d = 0; d < 64; ++d) { v[d] = q[base + (size_t)d * N_PIX]; m = fmaxf(m, v[d]); }
    float s = 0.f;
#pragma unroll
    for (int d = 0; d < 64; ++d) { v[d] = expf(v[d] - m); s += v[d]; }
    float inv = 0.125f / s;
#pragma unroll
    for (int d = 0; d < 64; ++d) {
        bf16 h, l; fsplit(v[d] * inv, h, l);
        qhi[base + (size_t)d * N_PIX] = h;
        qlo[base + (size_t)d * N_PIX] = l;
    }
}

// ---------------- softmax over spatial N (16384) for k; emit hi/lo ----------------
__global__ void __launch_bounds__(256) k_softmax_k(const float* __restrict__ kin,
                                                   bf16* __restrict__ khi, bf16* __restrict__ klo)
{
    int row = blockIdx.x;                 // b*512 + ch
    const float4* b4 = (const float4*)(kin + (size_t)row * N_PIX);
    size_t ob = (size_t)row * N_PIX;
    int t = threadIdx.x, lane = t & 31, warp = t >> 5;
    __shared__ float red[40];

    float4 r[16];
    float m = -3.4e38f;
#pragma unroll
    for (int i = 0; i < 16; ++i) {
        r[i] = b4[t + i * 256];
        m = fmaxf(m, fmaxf(fmaxf(r[i].x, r[i].y), fmaxf(r[i].z, r[i].w)));
    }
#pragma unroll
    for (int o = 16; o; o >>= 1) m = fmaxf(m, __shfl_xor_sync(0xffffffffu, m, o));
    if (lane == 0) red[warp] = m;
    __syncthreads();
    if (t == 0) { float mm = red[0]; for (int w = 1; w < 8; ++w) mm = fmaxf(mm, red[w]); red[32] = mm; }
    __syncthreads();
    m = red[32];

    float s = 0.f;
#pragma unroll
    for (int i = 0; i < 16; ++i) {
        r[i].x = expf(r[i].x - m); r[i].y = expf(r[i].y - m);
        r[i].z = expf(r[i].z - m); r[i].w = expf(r[i].w - m);
        s += r[i].x + r[i].y + r[i].z + r[i].w;
    }
#pragma unroll
    for (int o = 16; o; o >>= 1) s += __shfl_xor_sync(0xffffffffu, s, o);
    if (lane == 0) red[warp] = s;
    __syncthreads();
    if (t == 0) { float tt = 0.f; for (int w = 0; w < 8; ++w) tt += red[w]; red[33] = tt; }
    __syncthreads();
    float inv = 1.0f / red[33];
#pragma unroll
    for (int i = 0; i < 16; ++i) {
        bf16 h0, l0, h1, l1, h2, l2, h3, l3;
        fsplit(r[i].x * inv, h0, l0); fsplit(r[i].y * inv, h1, l1);
        fsplit(r[i].z * inv, h2, l2); fsplit(r[i].w * inv, h3, l3);
        size_t o = ob + (size_t)(t + i * 256) * 4;
        *(uint2*)(khi + o) = make_uint2(pack2(h0, h1), pack2(h2, h3));
        *(uint2*)(klo + o) = make_uint2(pack2(l0, l1), pack2(l2, l3));
    }
}

// ---------------- context partials (tensor): P[bh,s][e][d] = sum_n v[e,n]*k[d,n] ----------------
__global__ void __launch_bounds__(256, 2) k_ctx_t(
    const bf16* __restrict__ khi, const bf16* __restrict__ klo,
    const bf16* __restrict__ vhi, const bf16* __restrict__ vlo,
    float* __restrict__ part)
{
    constexpr int P = 72;
    __shared__ bf16 Vs[2][64 * P];
    __shared__ bf16 Ks[2][64 * P];

    int t = threadIdx.x, warp = t >> 5, lane = t & 31;
    int wm = warp & 1, wn = warp >> 1;        // 2 x 4; warp tile 32(e) x 16(d)
    int g = lane >> 2, tig = lane & 3;
    int bh = blockIdx.x >> 3, s = blockIdx.x & 7;
    size_t cb = (size_t)bh * 64 * N_PIX + (size_t)s * 2048;

    const uint32_t vB0 = s2u(&Vs[0][0]), vB1 = s2u(&Vs[1][0]);
    const uint32_t kB0 = s2u(&Ks[0][0]), kB1 = s2u(&Ks[1][0]);

    float acc[2][2][4];
#pragma unroll
    for (int m = 0; m < 2; ++m)
#pragma unroll
        for (int n = 0; n < 2; ++n)
#pragma unroll
            for (int r = 0; r < 4; ++r) acc[m][n][r] = 0.f;

    const int l15 = lane & 15, hi8 = (lane >> 4) * 8;
    const int bg = lane >> 3, bl = lane & 7;
    const int brow = (bg >> 1) * 8 + bl;      // B x4 non-trans: n-row within 16
    const int bcol = (bg & 1) * 8;            // k-half

    for (int it = 0; it < 32; ++it) {
        __syncthreads();
#pragma unroll
        for (int i = t; i < 512; i += 256) {  // 64 rows x 64 el, 4 plane-mats
            int row = i >> 3, c8 = (i & 7) * 8;
            size_t src = cb + (size_t)row * N_PIX + it * 64 + c8;
            *(uint4*)&Ks[0][row * P + c8] = *(const uint4*)(khi + src);
            *(uint4*)&Ks[1][row * P + c8] = *(const uint4*)(klo + src);
            *(uint4*)&Vs[0][row * P + c8] = *(const uint4*)(vhi + src);
            *(uint4*)&Vs[1][row * P + c8] = *(const uint4*)(vlo + src);
        }
        __syncthreads();

#pragma unroll
        for (int ks = 0; ks < 64; ks += 16) {
            uint32_t bh_[2][2], bl_[2][2], r[4];
            uint32_t boff = (uint32_t)((wn * 16 + brow) * P + ks + bcol) * 2;
            ldsm4(r, kB0 + boff);
            bh_[0][0] = r[0]; bh_[0][1] = r[1]; bh_[1][0] = r[2]; bh_[1][1] = r[3];
            ldsm4(r, kB1 + boff);
            bl_[0][0] = r[0]; bl_[0][1] = r[1]; bl_[1][0] = r[2]; bl_[1][1] = r[3];
#pragma unroll
            for (int mt = 0; mt < 2; ++mt) {
                uint32_t ah[4], al[4];
                uint32_t aoff = (uint32_t)((wm * 32 + mt * 16 + l15) * P + ks + hi8) * 2;
                ldsm4(ah, vB0 + aoff);
                ldsm4(al, vB1 + aoff);
#pragma unroll
                for (int nt = 0; nt < 2; ++nt) {
                    mma_bf16(acc[mt][nt], ah, bh_[nt]);
                    mma_bf16(acc[mt][nt], al, bh_[nt]);
                    mma_bf16(acc[mt][nt], ah, bl_[nt]);
                }
            }
        }
    }

    size_t ob = (size_t)blockIdx.x * 4096;
#pragma unroll
    for (int mt = 0; mt < 2; ++mt)
#pragma unroll
        for (int h2 = 0; h2 < 2; ++h2) {
            int e = wm * 32 + mt * 16 + g + h2 * 8;
#pragma unroll
            for (int nt = 0; nt < 2; ++nt) {
                int d = wn * 16 + nt * 8 + tig * 2;
                *(float2*)&part[ob + (size_t)e * 64 + d] =
                    make_float2(acc[mt][nt][h2 * 2], acc[mt][nt][h2 * 2 + 1]);
            }
        }
}

// ---------------- reduce partials; emit ctx^T hi/lo [bh][e][d] ----------------
__global__ void k_ctx_reduce(const float* __restrict__ part,
                             bf16* __restrict__ chi, bf16* __restrict__ clo)
{
    int i = blockIdx.x * 256 + threadIdx.x;    // < 262144
    int bh = i >> 12, ed = i & 4095;
    float s = 0.f;
#pragma unroll
    for (int ss = 0; ss < 8; ++ss)
        s += part[((size_t)bh * 8 + ss) * 4096 + ed];
    bf16 h, l; fsplit(s, h, l);
    chi[i] = h; clo[i] = l;
}

// ---------------- launch ----------------
extern "C" void kernel_launch(void* const* d_in, const int* in_sizes, int n_in,
                              void* d_out, int out_size)
{
    const float* fmap  = (const float*)d_in[0];
    const float* w_q   = (const float*)d_in[1];
    const float* w_dw  = (const float*)d_in[2];
    const float* w_pw  = (const float*)d_in[3];
    const float* w_out = (const float*)d_in[4];
    const float* b_out = (const float*)d_in[5];
    float* out = (float*)d_out;

    float *q, *k, *part;
    bf16 *fhi, *flo, *dwhi, *dwlo, *qhi, *qlo, *khi, *klo, *vhi, *vlo;
    bf16 *avhi, *avlo, *chi, *clo, *wqh, *wql, *wph, *wpl, *woh, *wol;
    cudaGetSymbolAddress((void**)&q,    g_q);
    cudaGetSymbolAddress((void**)&k,    g_k);
    cudaGetSymbolAddress((void**)&part, g_part);
    cudaGetSymbolAddress((void**)&fhi,  g_fhi);   cudaGetSymbolAddress((void**)&flo,  g_flo);
    cudaGetSymbolAddress((void**)&dwhi, g_dwhi);  cudaGetSymbolAddress((void**)&dwlo, g_dwlo);
    cudaGetSymbolAddress((void**)&qhi,  g_qhi);   cudaGetSymbolAddress((void**)&qlo,  g_qlo);
    cudaGetSymbolAddress((void**)&khi,  g_khi);   cudaGetSymbolAddress((void**)&klo,  g_klo);
    cudaGetSymbolAddress((void**)&vhi,  g_vhi);   cudaGetSymbolAddress((void**)&vlo,  g_vlo);
    cudaGetSymbolAddress((void**)&avhi, g_avhi);  cudaGetSymbolAddress((void**)&avlo, g_avlo);
    cudaGetSymbolAddress((void**)&chi,  g_ctxhi); cudaGetSymbolAddress((void**)&clo,  g_ctxlo);
    cudaGetSymbolAddress((void**)&wqh,  g_wqhi);  cudaGetSymbolAddress((void**)&wql,  g_wqlo);
    cudaGetSymbolAddress((void**)&wph,  g_wpwhi); cudaGetSymbolAddress((void**)&wpl,  g_wpwlo);
    cudaGetSymbolAddress((void**)&woh,  g_wohi);  cudaGetSymbolAddress((void**)&wol,  g_wolo);

    // 0) weight splits
    k_cvt<<<512, 256>>>(w_q, wqh, wql, 512 * 256);
    k_cvt<<<1024, 256>>>(w_pw, wph, wpl, 1024 * 256);
    k_cvt<<<512, 256>>>(w_out, woh, wol, 256 * 512);

    // 1) depthwise 3x3 + fmap/dw hi-lo planes
    k_dwconv<<<dim3(64, BATCH * 256), 256>>>(fmap, w_dw);

    // 2) q = w_q @ fmap  (fp32 out)
    k_mma_gemm<128, 0><<<dim3(128, 4, 8), 256>>>(
        wqh, wql, fhi, flo, nullptr, q, nullptr, nullptr,
        256, 0, 256LL * N_PIX, 512LL * N_PIX);

    // 3a) k = w_pw[0:512] @ dw  (fp32 out)
    k_mma_gemm<128, 0><<<dim3(128, 4, 8), 256>>>(
        wph, wpl, dwhi, dwlo, nullptr, k, nullptr, nullptr,
        256, 0, 256LL * N_PIX, 512LL * N_PIX);

    // 3b) v = w_pw[512:1024] @ dw  (hi/lo out)
    k_mma_gemm<128, 1><<<dim3(128, 4, 8), 256>>>(
        wph + 512 * 256, wpl + 512 * 256, dwhi, dwlo, nullptr,
        nullptr, vhi, vlo, 256, 0, 256LL * N_PIX, 512LL * N_PIX);

    // 4) softmax over d for q -> hi/lo
    k_softmax_q<<<4096, 256>>>(q, qhi, qlo);

    // 5) softmax over N for k -> hi/lo
    k_softmax_k<<<4096, 256>>>(k, khi, klo);

    // 6) context: tensor split-K partials + reduce -> ctx^T hi/lo
    k_ctx_t<<<512, 256>>>(khi, klo, vhi, vlo, part);
    k_ctx_reduce<<<1024, 256>>>(part, chi, clo);

    // 7) av = gelu(ctx^T @ q)  batched over 64 (b,h)  (hi/lo out)
    k_mma_gemm<64, 2><<<dim3(128, 1, 64), 256>>>(
        chi, clo, qhi, qlo, nullptr, nullptr, avhi, avlo,
        64, 4096LL, 64LL * N_PIX, 64LL * N_PIX);

    // 8) out = w_out @ av + b_out  (fp32 + bias)
    k_mma_gemm<128, 3><<<dim3(128, 2, 8), 256>>>(
        woh, wol, avhi, avlo, b_out, out, nullptr, nullptr,
        512, 0, 512LL * N_PIX, 256LL * N_PIX);
}

// round 6
// speedup vs baseline: 2.1551x; 1.1403x over previous
#include <cuda_runtime.h>
#include <cuda_bf16.h>
#include <math.h>
#include <stdint.h>

#define N_PIX  16384
#define BATCH  8

typedef __nv_bfloat16 bf16;

// ---------------- scratch (static device globals; no allocation) ----------------
__device__ __align__(16) float g_k   [(size_t)BATCH * 512 * N_PIX];   // k fp32 pre-softmax
__device__ __align__(16) float g_part[64 * 8 * 64 * 64];

__device__ __align__(16) bf16 g_fhi [(size_t)BATCH * 256 * N_PIX];
__device__ __align__(16) bf16 g_flo [(size_t)BATCH * 256 * N_PIX];
__device__ __align__(16) bf16 g_dwhi[(size_t)BATCH * 256 * N_PIX];
__device__ __align__(16) bf16 g_dwlo[(size_t)BATCH * 256 * N_PIX];
__device__ __align__(16) bf16 g_qhi [(size_t)BATCH * 512 * N_PIX];
__device__ __align__(16) bf16 g_qlo [(size_t)BATCH * 512 * N_PIX];
__device__ __align__(16) bf16 g_khi [(size_t)BATCH * 512 * N_PIX];
__device__ __align__(16) bf16 g_klo [(size_t)BATCH * 512 * N_PIX];
__device__ __align__(16) bf16 g_vhi [(size_t)BATCH * 512 * N_PIX];
__device__ __align__(16) bf16 g_vlo [(size_t)BATCH * 512 * N_PIX];
__device__ __align__(16) bf16 g_avhi[(size_t)BATCH * 512 * N_PIX];
__device__ __align__(16) bf16 g_avlo[(size_t)BATCH * 512 * N_PIX];
__device__ __align__(16) bf16 g_ctxhi[64 * 64 * 64];
__device__ __align__(16) bf16 g_ctxlo[64 * 64 * 64];
__device__ __align__(16) bf16 g_wqhi [512 * 256],  g_wqlo [512 * 256];
__device__ __align__(16) bf16 g_wpwhi[1024 * 256], g_wpwlo[1024 * 256];
__device__ __align__(16) bf16 g_wohi [256 * 512],  g_wolo [256 * 512];

// ---------------- helpers ----------------
__device__ __forceinline__ float gelu_exact(float x) { return x * normcdff(x); }
__device__ __forceinline__ void fsplit(float x, bf16& h, bf16& l) {
    h = __float2bfloat16_rn(x);
    l = __float2bfloat16_rn(x - __bfloat162float(h));
}
__device__ __forceinline__ uint32_t pack2(bf16 a, bf16 b) {
    __nv_bfloat162 t; t.x = a; t.y = b;
    return *reinterpret_cast<uint32_t*>(&t);
}
__device__ __forceinline__ void mma_bf16(float d[4], const uint32_t a[4], const uint32_t b[2]) {
    asm volatile("mma.sync.aligned.m16n8k16.row.col.f32.bf16.bf16.f32 "
                 "{%0,%1,%2,%3}, {%4,%5,%6,%7}, {%8,%9}, {%0,%1,%2,%3};"
                 : "+f"(d[0]), "+f"(d[1]), "+f"(d[2]), "+f"(d[3])
                 : "r"(a[0]), "r"(a[1]), "r"(a[2]), "r"(a[3]), "r"(b[0]), "r"(b[1]));
}
__device__ __forceinline__ void ldsm4(uint32_t r[4], uint32_t addr) {
    asm volatile("ldmatrix.sync.aligned.m8n8.x4.shared.b16 {%0,%1,%2,%3}, [%4];"
                 : "=r"(r[0]), "=r"(r[1]), "=r"(r[2]), "=r"(r[3]) : "r"(addr));
}
__device__ __forceinline__ void ldsm4t(uint32_t r[4], uint32_t addr) {
    asm volatile("ldmatrix.sync.aligned.m8n8.x4.trans.shared.b16 {%0,%1,%2,%3}, [%4];"
                 : "=r"(r[0]), "=r"(r[1]), "=r"(r[2]), "=r"(r[3]) : "r"(addr));
}
__device__ __forceinline__ uint32_t s2u(const void* p) {
    return (uint32_t)__cvta_generic_to_shared(p);
}
__device__ __forceinline__ void cpa16(uint32_t dst, const void* src) {
    asm volatile("cp.async.cg.shared.global [%0], [%1], 16;" :: "r"(dst), "l"(src));
}
__device__ __forceinline__ void cp_commit() {
    asm volatile("cp.async.commit_group;");
}
template <int N>
__device__ __forceinline__ void cp_wait() {
    asm volatile("cp.async.wait_group %0;" :: "n"(N));
}

// ---------------- weight convert: fp32 -> bf16 hi/lo ----------------
__global__ void k_cvt(const float* __restrict__ x, bf16* __restrict__ hi,
                      bf16* __restrict__ lo, int n)
{
    int i = blockIdx.x * 256 + threadIdx.x;
    if (i < n) { bf16 h, l; fsplit(x[i], h, l); hi[i] = h; lo[i] = l; }
}

// ---------------- depthwise 3x3 (pad 1); 4 px/thread; emit dw & fmap hi/lo ----------------
__global__ void __launch_bounds__(256) k_dwconv(const float* __restrict__ in,
                                                const float* __restrict__ wdw)
{
    int plane = blockIdx.y;              // b*256 + c
    int c = plane & 255;
    const float* ip = in + (size_t)plane * N_PIX;

    float w[9];
#pragma unroll
    for (int k = 0; k < 9; ++k) w[k] = __ldg(wdw + c * 9 + k);

    int p4 = (blockIdx.x * 256 + threadIdx.x) * 4;
    int y = p4 >> 7, x0 = p4 & 127;

    float L[3][6];
#pragma unroll
    for (int r = 0; r < 3; ++r) {
        int yy = y + r - 1;
        if (yy < 0 || yy > 127) {
#pragma unroll
            for (int j = 0; j < 6; ++j) L[r][j] = 0.f;
        } else {
            const float* rp = ip + yy * 128 + x0;
            float4 f = *(const float4*)rp;
            L[r][1] = f.x; L[r][2] = f.y; L[r][3] = f.z; L[r][4] = f.w;
            L[r][0] = (x0 > 0)   ? __ldg(rp - 1) : 0.f;
            L[r][5] = (x0 < 124) ? __ldg(rp + 4) : 0.f;
        }
    }

    bf16 h[4], l[4];
    size_t o = (size_t)plane * N_PIX + p4;
#pragma unroll
    for (int i = 0; i < 4; ++i) {
        float s = 0.f;
#pragma unroll
        for (int r = 0; r < 3; ++r)
#pragma unroll
            for (int dx = 0; dx < 3; ++dx)
                s += L[r][i + dx] * w[r * 3 + dx];
        fsplit(s, h[i], l[i]);
    }
    *(uint2*)(g_dwhi + o) = make_uint2(pack2(h[0], h[1]), pack2(h[2], h[3]));
    *(uint2*)(g_dwlo + o) = make_uint2(pack2(l[0], l[1]), pack2(l[2], l[3]));
#pragma unroll
    for (int i = 0; i < 4; ++i) fsplit(L[1][1 + i], h[i], l[i]);
    *(uint2*)(g_fhi + o) = make_uint2(pack2(h[0], h[1]), pack2(h[2], h[3]));
    *(uint2*)(g_flo + o) = make_uint2(pack2(l[0], l[1]), pack2(l[2], l[3]));
}

// ---------------- split-bf16 tensor-core GEMM with 2-stage cp.async pipeline ----------------
// Y[o,p] = sum_c A[o,c] * X[c,p].  A hi/lo row-major [O,C]; X hi/lo [C,N_PIX].
// MODE: 0 fp32 out, 1 hl out, 2 gelu+hl out, 3 bias+fp32 out, 4 softmax-over-d(64)+scale+hl out.
template <int BM, int MODE>
__global__ void __launch_bounds__(256, 2) k_mma_gemm(
    const bf16* __restrict__ Ahi, const bf16* __restrict__ Alo,
    const bf16* __restrict__ Bhi, const bf16* __restrict__ Blo,
    const float* __restrict__ bias,
    float* __restrict__ Yf, bf16* __restrict__ Yhi, bf16* __restrict__ Ylo,
    int C, long long as_, long long xs, long long ys)
{
    constexpr int BN = 128, BK = 32, AP = 40, BP = 136;
    constexpr int WM = BM / 2, MT = WM / 16;
    constexpr uint32_t APl = BM * AP * 2;   // bytes per A plane
    constexpr uint32_t BPl = BK * BP * 2;

    extern __shared__ __align__(16) bf16 smp[];

    const int t = threadIdx.x, warp = t >> 5, lane = t & 31;
    const int wm = warp & 1, wn = warp >> 1;
    const int g = lane >> 2, tig = lane & 3;
    const int pblk = blockIdx.x * BN, o0 = blockIdx.y * BM;
    const long long z = blockIdx.z;
    const bf16* AH = Ahi + z * as_;
    const bf16* AL = Alo + z * as_;
    const bf16* XH = Bhi + z * xs;
    const bf16* XL = Blo + z * xs;

    const uint32_t Abase = s2u(smp);
    const uint32_t Bbase = Abase + 4 * APl;

#define LOAD_STAGE(st, c0v) do {                                              \
    uint32_t aD = Abase + (uint32_t)(st) * 2 * APl;                           \
    uint32_t bD = Bbase + (uint32_t)(st) * 2 * BPl;                           \
    for (int i = t; i < BM * 4; i += 256) {                                   \
        int m_ = i >> 2, kq = (i & 3) * 8;                                    \
        size_t src = (size_t)(o0 + m_) * C + (c0v) + kq;                      \
        uint32_t d_ = (uint32_t)(m_ * AP + kq) * 2;                           \
        cpa16(aD + d_, AH + src);                                             \
        cpa16(aD + APl + d_, AL + src);                                       \
    }                                                                         \
    for (int i = t; i < 512; i += 256) {                                      \
        int cc = i >> 4, pq = (i & 15) * 8;                                   \
        size_t src = (size_t)((c0v) + cc) * N_PIX + pblk + pq;                \
        uint32_t d_ = (uint32_t)(cc * BP + pq) * 2;                           \
        cpa16(bD + d_, XH + src);                                             \
        cpa16(bD + BPl + d_, XL + src);                                       \
    }                                                                         \
    cp_commit();                                                              \
} while (0)

    float acc[MT][4][4];
#pragma unroll
    for (int m = 0; m < MT; ++m)
#pragma unroll
        for (int n = 0; n < 4; ++n)
#pragma unroll
            for (int r = 0; r < 4; ++r) acc[m][n][r] = 0.f;

    const int l15 = lane & 15;
    const int hi8 = (lane >> 4) * 8;

    const int T = C >> 5;
    LOAD_STAGE(0, 0);

    for (int it = 0; it < T; ++it) {
        const int st = it & 1;
        if (it + 1 < T) { LOAD_STAGE(st ^ 1, (it + 1) * BK); cp_wait<1>(); }
        else cp_wait<0>();
        __syncthreads();

        const uint32_t a0 = Abase + (uint32_t)st * 2 * APl;
        const uint32_t a1 = a0 + APl;
        const uint32_t b0 = Bbase + (uint32_t)st * 2 * BPl;
        const uint32_t b1 = b0 + BPl;

#pragma unroll
        for (int ks = 0; ks < BK; ks += 16) {
            uint32_t bh_[4][2], bl_[4][2], r[4];
#pragma unroll
            for (int nn = 0; nn < 2; ++nn) {
                uint32_t off = (uint32_t)((ks + l15) * BP + wn * 32 + nn * 16 + hi8) * 2;
                ldsm4t(r, b0 + off);
                bh_[nn*2][0] = r[0]; bh_[nn*2][1] = r[1];
                bh_[nn*2+1][0] = r[2]; bh_[nn*2+1][1] = r[3];
                ldsm4t(r, b1 + off);
                bl_[nn*2][0] = r[0]; bl_[nn*2][1] = r[1];
                bl_[nn*2+1][0] = r[2]; bl_[nn*2+1][1] = r[3];
            }
#pragma unroll
            for (int mt = 0; mt < MT; ++mt) {
                uint32_t ah[4], al[4];
                uint32_t off = (uint32_t)((wm * WM + mt * 16 + l15) * AP + ks + hi8) * 2;
                ldsm4(ah, a0 + off);
                ldsm4(al, a1 + off);
#pragma unroll
                for (int nt = 0; nt < 4; ++nt) {
                    mma_bf16(acc[mt][nt], ah, bh_[nt]);
                    mma_bf16(acc[mt][nt], al, bh_[nt]);
                    mma_bf16(acc[mt][nt], ah, bl_[nt]);
                }
            }
        }
        __syncthreads();
    }
#undef LOAD_STAGE

    if (MODE == 4) {
        // softmax over the 64 rows of this warp-half (one head), per pixel column; *1/8
        float sc[8];
#pragma unroll
        for (int nt = 0; nt < 4; ++nt)
#pragma unroll
            for (int c = 0; c < 2; ++c) {
                float m = -3.4e38f;
#pragma unroll
                for (int mt = 0; mt < MT; ++mt) {
                    m = fmaxf(m, acc[mt][nt][c]);
                    m = fmaxf(m, acc[mt][nt][2 + c]);
                }
                m = fmaxf(m, __shfl_xor_sync(0xffffffffu, m, 4));
                m = fmaxf(m, __shfl_xor_sync(0xffffffffu, m, 8));
                m = fmaxf(m, __shfl_xor_sync(0xffffffffu, m, 16));
                float s = 0.f;
#pragma unroll
                for (int mt = 0; mt < MT; ++mt) {
                    float e0 = expf(acc[mt][nt][c] - m);
                    float e1 = expf(acc[mt][nt][2 + c] - m);
                    acc[mt][nt][c] = e0; acc[mt][nt][2 + c] = e1;
                    s += e0 + e1;
                }
                s += __shfl_xor_sync(0xffffffffu, s, 4);
                s += __shfl_xor_sync(0xffffffffu, s, 8);
                s += __shfl_xor_sync(0xffffffffu, s, 16);
                sc[nt * 2 + c] = 0.125f / s;
            }
#pragma unroll
        for (int mt = 0; mt < MT; ++mt)
#pragma unroll
            for (int h2 = 0; h2 < 2; ++h2) {
                int rrow = o0 + wm * WM + mt * 16 + g + h2 * 8;
#pragma unroll
                for (int nt = 0; nt < 4; ++nt) {
                    int p = pblk + wn * 32 + nt * 8 + tig * 2;
                    float v0 = acc[mt][nt][h2 * 2 + 0] * sc[nt * 2 + 0];
                    float v1 = acc[mt][nt][h2 * 2 + 1] * sc[nt * 2 + 1];
                    size_t o = (size_t)rrow * N_PIX + p;
                    bf16 h0, l0, h1, l1;
                    fsplit(v0, h0, l0); fsplit(v1, h1, l1);
                    *(uint32_t*)(Yhi + z * ys + o) = pack2(h0, h1);
                    *(uint32_t*)(Ylo + z * ys + o) = pack2(l0, l1);
                }
            }
        return;
    }

#pragma unroll
    for (int mt = 0; mt < MT; ++mt) {
#pragma unroll
        for (int h2 = 0; h2 < 2; ++h2) {
            int rrow = o0 + wm * WM + mt * 16 + g + h2 * 8;
            float bb = (MODE == 3) ? __ldg(&bias[rrow]) : 0.f;
#pragma unroll
            for (int nt = 0; nt < 4; ++nt) {
                int p = pblk + wn * 32 + nt * 8 + tig * 2;
                float v0 = acc[mt][nt][h2 * 2 + 0] + bb;
                float v1 = acc[mt][nt][h2 * 2 + 1] + bb;
                size_t o = (size_t)rrow * N_PIX + p;
                if (MODE == 0 || MODE == 3) {
                    *(float2*)(Yf + z * ys + o) = make_float2(v0, v1);
                } else {
                    if (MODE == 2) { v0 = gelu_exact(v0); v1 = gelu_exact(v1); }
                    bf16 h0, l0, h1, l1;
                    fsplit(v0, h0, l0); fsplit(v1, h1, l1);
                    *(uint32_t*)(Yhi + z * ys + o) = pack2(h0, h1);
                    *(uint32_t*)(Ylo + z * ys + o) = pack2(l0, l1);
                }
            }
        }
    }
}

// ---------------- softmax over spatial N (16384) for k; emit hi/lo ----------------
__global__ void __launch_bounds__(256) k_softmax_k(const float* __restrict__ kin,
                                                   bf16* __restrict__ khi, bf16* __restrict__ klo)
{
    int row = blockIdx.x;
    const float4* b4 = (const float4*)(kin + (size_t)row * N_PIX);
    size_t ob = (size_t)row * N_PIX;
    int t = threadIdx.x, lane = t & 31, warp = t >> 5;
    __shared__ float red[40];

    float4 r[16];
    float m = -3.4e38f;
#pragma unroll
    for (int i = 0; i < 16; ++i) {
        r[i] = b4[t + i * 256];
        m = fmaxf(m, fmaxf(fmaxf(r[i].x, r[i].y), fmaxf(r[i].z, r[i].w)));
    }
#pragma unroll
    for (int o = 16; o; o >>= 1) m = fmaxf(m, __shfl_xor_sync(0xffffffffu, m, o));
    if (lane == 0) red[warp] = m;
    __syncthreads();
    if (t == 0) { float mm = red[0]; for (int w = 1; w < 8; ++w) mm = fmaxf(mm, red[w]); red[32] = mm; }
    __syncthreads();
    m = red[32];

    float s = 0.f;
#pragma unroll
    for (int i = 0; i < 16; ++i) {
        r[i].x = expf(r[i].x - m); r[i].y = expf(r[i].y - m);
        r[i].z = expf(r[i].z - m); r[i].w = expf(r[i].w - m);
        s += r[i].x + r[i].y + r[i].z + r[i].w;
    }
#pragma unroll
    for (int o = 16; o; o >>= 1) s += __shfl_xor_sync(0xffffffffu, s, o);
    if (lane == 0) red[warp] = s;
    __syncthreads();
    if (t == 0) { float tt = 0.f; for (int w = 0; w < 8; ++w) tt += red[w]; red[33] = tt; }
    __syncthreads();
    float inv = 1.0f / red[33];
#pragma unroll
    for (int i = 0; i < 16; ++i) {
        bf16 h0, l0, h1, l1, h2, l2, h3, l3;
        fsplit(r[i].x * inv, h0, l0); fsplit(r[i].y * inv, h1, l1);
        fsplit(r[i].z * inv, h2, l2); fsplit(r[i].w * inv, h3, l3);
        size_t o = ob + (size_t)(t + i * 256) * 4;
        *(uint2*)(khi + o) = make_uint2(pack2(h0, h1), pack2(h2, h3));
        *(uint2*)(klo + o) = make_uint2(pack2(l0, l1), pack2(l2, l3));
    }
}

// ---------------- context partials (tensor, pipelined): P[bh,s][e][d] ----------------
__global__ void __launch_bounds__(256, 2) k_ctx_t(
    const bf16* __restrict__ khi, const bf16* __restrict__ klo,
    const bf16* __restrict__ vhi, const bf16* __restrict__ vlo,
    float* __restrict__ part)
{
    constexpr int P = 72;
    constexpr uint32_t ASZ = 64 * P * 2;          // bytes per array
    extern __shared__ __align__(16) bf16 smp[];

    int t = threadIdx.x, warp = t >> 5, lane = t & 31;
    int wm = warp & 1, wn = warp >> 1;
    int g = lane >> 2, tig = lane & 3;
    int bh = blockIdx.x >> 3, s = blockIdx.x & 7;
    size_t cb = (size_t)bh * 64 * N_PIX + (size_t)s * 2048;

    const uint32_t base = s2u(smp);
#define CARR(st, a) (base + ((uint32_t)(st) * 4 + (a)) * ASZ)

#define CTX_LOAD(st, itv) do {                                                \
    for (int i = t; i < 512; i += 256) {                                      \
        int row = i >> 3, c8 = (i & 7) * 8;                                   \
        size_t src = cb + (size_t)row * N_PIX + (itv) * 64 + c8;              \
        uint32_t d_ = (uint32_t)(row * P + c8) * 2;                           \
        cpa16(CARR(st, 0) + d_, khi + src);                                   \
        cpa16(CARR(st, 1) + d_, klo + src);                                   \
        cpa16(CARR(st, 2) + d_, vhi + src);                                   \
        cpa16(CARR(st, 3) + d_, vlo + src);                                   \
    }                                                                         \
    cp_commit();                                                              \
} while (0)

    float acc[2][2][4];
#pragma unroll
    for (int m = 0; m < 2; ++m)
#pragma unroll
        for (int n = 0; n < 2; ++n)
#pragma unroll
            for (int r = 0; r < 4; ++r) acc[m][n][r] = 0.f;

    const int l15 = lane & 15, hi8 = (lane >> 4) * 8;
    const int bg = lane >> 3, bl = lane & 7;
    const int brow = (bg >> 1) * 8 + bl;
    const int bcol = (bg & 1) * 8;

    CTX_LOAD(0, 0);
    for (int it = 0; it < 32; ++it) {
        int st = it & 1;
        if (it + 1 < 32) { CTX_LOAD(st ^ 1, it + 1); cp_wait<1>(); }
        else cp_wait<0>();
        __syncthreads();

        const uint32_t kB0 = CARR(st, 0), kB1 = CARR(st, 1);
        const uint32_t vB0 = CARR(st, 2), vB1 = CARR(st, 3);

#pragma unroll
        for (int ks = 0; ks < 64; ks += 16) {
            uint32_t bh_[2][2], bl_[2][2], r[4];
            uint32_t boff = (uint32_t)((wn * 16 + brow) * P + ks + bcol) * 2;
            ldsm4(r, kB0 + boff);
            bh_[0][0] = r[0]; bh_[0][1] = r[1]; bh_[1][0] = r[2]; bh_[1][1] = r[3];
            ldsm4(r, kB1 + boff);
            bl_[0][0] = r[0]; bl_[0][1] = r[1]; bl_[1][0] = r[2]; bl_[1][1] = r[3];
#pragma unroll
            for (int mt = 0; mt < 2; ++mt) {
                uint32_t ah[4], al[4];
                uint32_t aoff = (uint32_t)((wm * 32 + mt * 16 + l15) * P + ks + hi8) * 2;
                ldsm4(ah, vB0 + aoff);
                ldsm4(al, vB1 + aoff);
#pragma unroll
                for (int nt = 0; nt < 2; ++nt) {
                    mma_bf16(acc[mt][nt], ah, bh_[nt]);
                    mma_bf16(acc[mt][nt], al, bh_[nt]);
                    mma_bf16(acc[mt][nt], ah, bl_[nt]);
                }
            }
        }
        __syncthreads();
    }
#undef CTX_LOAD
#undef CARR

    size_t ob = (size_t)blockIdx.x * 4096;
#pragma unroll
    for (int mt = 0; mt < 2; ++mt)
#pragma unroll
        for (int h2 = 0; h2 < 2; ++h2) {
            int e = wm * 32 + mt * 16 + g + h2 * 8;
#pragma unroll
            for (int nt = 0; nt < 2; ++nt) {
                int d = wn * 16 + nt * 8 + tig * 2;
                *(float2*)&part[ob + (size_t)e * 64 + d] =
                    make_float2(acc[mt][nt][h2 * 2], acc[mt][nt][h2 * 2 + 1]);
            }
        }
}

// ---------------- reduce partials; emit ctx^T hi/lo [bh][e][d] ----------------
__global__ void k_ctx_reduce(const float* __restrict__ part,
                             bf16* __restrict__ chi, bf16* __restrict__ clo)
{
    int i = blockIdx.x * 256 + threadIdx.x;
    int bh = i >> 12, ed = i & 4095;
    float s = 0.f;
#pragma unroll
    for (int ss = 0; ss < 8; ++ss)
        s += part[((size_t)bh * 8 + ss) * 4096 + ed];
    bf16 h, l; fsplit(s, h, l);
    chi[i] = h; clo[i] = l;
}

// ---------------- launch ----------------
extern "C" void kernel_launch(void* const* d_in, const int* in_sizes, int n_in,
                              void* d_out, int out_size)
{
    const float* fmap  = (const float*)d_in[0];
    const float* w_q   = (const float*)d_in[1];
    const float* w_dw  = (const float*)d_in[2];
    const float* w_pw  = (const float*)d_in[3];
    const float* w_out = (const float*)d_in[4];
    const float* b_out = (const float*)d_in[5];
    float* out = (float*)d_out;

    float *k, *part;
    bf16 *fhi, *flo, *dwhi, *dwlo, *qhi, *qlo, *khi, *klo, *vhi, *vlo;
    bf16 *avhi, *avlo, *chi, *clo, *wqh, *wql, *wph, *wpl, *woh, *wol;
    cudaGetSymbolAddress((void**)&k,    g_k);
    cudaGetSymbolAddress((void**)&part, g_part);
    cudaGetSymbolAddress((void**)&fhi,  g_fhi);   cudaGetSymbolAddress((void**)&flo,  g_flo);
    cudaGetSymbolAddress((void**)&dwhi, g_dwhi);  cudaGetSymbolAddress((void**)&dwlo, g_dwlo);
    cudaGetSymbolAddress((void**)&qhi,  g_qhi);   cudaGetSymbolAddress((void**)&qlo,  g_qlo);
    cudaGetSymbolAddress((void**)&khi,  g_khi);   cudaGetSymbolAddress((void**)&klo,  g_klo);
    cudaGetSymbolAddress((void**)&vhi,  g_vhi);   cudaGetSymbolAddress((void**)&vlo,  g_vlo);
    cudaGetSymbolAddress((void**)&avhi, g_avhi);  cudaGetSymbolAddress((void**)&avlo, g_avlo);
    cudaGetSymbolAddress((void**)&chi,  g_ctxhi); cudaGetSymbolAddress((void**)&clo,  g_ctxlo);
    cudaGetSymbolAddress((void**)&wqh,  g_wqhi);  cudaGetSymbolAddress((void**)&wql,  g_wqlo);
    cudaGetSymbolAddress((void**)&wph,  g_wpwhi); cudaGetSymbolAddress((void**)&wpl,  g_wpwlo);
    cudaGetSymbolAddress((void**)&woh,  g_wohi);  cudaGetSymbolAddress((void**)&wol,  g_wolo);

    const int SM128 = 8 * (40 * 128 + 4352);   // 75776 B
    const int SM64  = 8 * (40 * 64 + 4352);    // 55296 B
    const int SMCTX = 2 * 4 * 64 * 72 * 2;     // 73728 B
    cudaFuncSetAttribute(k_mma_gemm<128,4>, cudaFuncAttributeMaxDynamicSharedMemorySize, SM128);
    cudaFuncSetAttribute(k_mma_gemm<128,0>, cudaFuncAttributeMaxDynamicSharedMemorySize, SM128);
    cudaFuncSetAttribute(k_mma_gemm<128,1>, cudaFuncAttributeMaxDynamicSharedMemorySize, SM128);
    cudaFuncSetAttribute(k_mma_gemm<128,3>, cudaFuncAttributeMaxDynamicSharedMemorySize, SM128);
    cudaFuncSetAttribute(k_mma_gemm<64,2>,  cudaFuncAttributeMaxDynamicSharedMemorySize, SM64);
    cudaFuncSetAttribute(k_ctx_t,           cudaFuncAttributeMaxDynamicSharedMemorySize, SMCTX);

    // 0) weight splits
    k_cvt<<<512, 256>>>(w_q, wqh, wql, 512 * 256);
    k_cvt<<<1024, 256>>>(w_pw, wph, wpl, 1024 * 256);
    k_cvt<<<512, 256>>>(w_out, woh, wol, 256 * 512);

    // 1) depthwise 3x3 + fmap/dw hi-lo planes (4 px/thread)
    k_dwconv<<<dim3(16, BATCH * 256), 256>>>(fmap, w_dw);

    // 2) q = softmax_d(w_q @ fmap) * 1/8  (fused, hl out)
    k_mma_gemm<128, 4><<<dim3(128, 4, 8), 256, SM128>>>(
        wqh, wql, fhi, flo, nullptr, nullptr, qhi, qlo,
        256, 0, 256LL * N_PIX, 512LL * N_PIX);

    // 3a) k = w_pw[0:512] @ dw  (fp32 out)
    k_mma_gemm<128, 0><<<dim3(128, 4, 8), 256, SM128>>>(
        wph, wpl, dwhi, dwlo, nullptr, k, nullptr, nullptr,
        256, 0, 256LL * N_PIX, 512LL * N_PIX);

    // 3b) v = w_pw[512:1024] @ dw  (hl out)
    k_mma_gemm<128, 1><<<dim3(128, 4, 8), 256, SM128>>>(
        wph + 512 * 256, wpl + 512 * 256, dwhi, dwlo, nullptr,
        nullptr, vhi, vlo, 256, 0, 256LL * N_PIX, 512LL * N_PIX);

    // 4) softmax over N for k -> hi/lo
    k_softmax_k<<<4096, 256>>>(k, khi, klo);

    // 5) context: pipelined tensor split-K partials + reduce
    k_ctx_t<<<512, 256, SMCTX>>>(khi, klo, vhi, vlo, part);
    k_ctx_reduce<<<1024, 256>>>(part, chi, clo);

    // 6) av = gelu(ctx^T @ q)  batched over 64 (b,h)  (hl out)
    k_mma_gemm<64, 2><<<dim3(128, 1, 64), 256, SM64>>>(
        chi, clo, qhi, qlo, nullptr, nullptr, avhi, avlo,
        64, 4096LL, 64LL * N_PIX, 64LL * N_PIX);

    // 7) out = w_out @ av + b_out  (fp32 + bias)
    k_mma_gemm<128, 3><<<dim3(128, 2, 8), 256, SM128>>>(
        woh, wol, avhi, avlo, b_out, out, nullptr, nullptr,
        512, 0, 512LL * N_PIX, 256LL * N_PIX);
}

// round 7
// speedup vs baseline: 2.1566x; 1.0007x over previous
#include <cuda_runtime.h>
#include <cuda_bf16.h>
#include <math.h>
#include <stdint.h>

#define N_PIX  16384
#define BATCH  8

typedef __nv_bfloat16 bf16;

// ---------------- scratch (static device globals; no allocation) ----------------
__device__ __align__(16) float g_k   [(size_t)BATCH * 512 * N_PIX];   // k fp32 pre-softmax
__device__ __align__(16) float g_part[64 * 8 * 64 * 64];

__device__ __align__(16) bf16 g_fhi [(size_t)BATCH * 256 * N_PIX];
__device__ __align__(16) bf16 g_flo [(size_t)BATCH * 256 * N_PIX];
__device__ __align__(16) bf16 g_dwhi[(size_t)BATCH * 256 * N_PIX];
__device__ __align__(16) bf16 g_dwlo[(size_t)BATCH * 256 * N_PIX];
__device__ __align__(16) bf16 g_qhi [(size_t)BATCH * 512 * N_PIX];
__device__ __align__(16) bf16 g_qlo [(size_t)BATCH * 512 * N_PIX];
__device__ __align__(16) bf16 g_khi [(size_t)BATCH * 512 * N_PIX];
__device__ __align__(16) bf16 g_klo [(size_t)BATCH * 512 * N_PIX];
__device__ __align__(16) bf16 g_vhi [(size_t)BATCH * 512 * N_PIX];
__device__ __align__(16) bf16 g_vlo [(size_t)BATCH * 512 * N_PIX];
__device__ __align__(16) bf16 g_avhi[(size_t)BATCH * 512 * N_PIX];
__device__ __align__(16) bf16 g_avlo[(size_t)BATCH * 512 * N_PIX];
__device__ __align__(16) bf16 g_ctxhi[64 * 64 * 64];
__device__ __align__(16) bf16 g_ctxlo[64 * 64 * 64];
__device__ __align__(16) bf16 g_wqhi [512 * 256],  g_wqlo [512 * 256];
__device__ __align__(16) bf16 g_wpwhi[1024 * 256], g_wpwlo[1024 * 256];
__device__ __align__(16) bf16 g_wohi [256 * 512],  g_wolo [256 * 512];

// ---------------- helpers ----------------
__device__ __forceinline__ float gelu_exact(float x) { return x * normcdff(x); }
__device__ __forceinline__ void fsplit(float x, bf16& h, bf16& l) {
    h = __float2bfloat16_rn(x);
    l = __float2bfloat16_rn(x - __bfloat162float(h));
}
__device__ __forceinline__ uint32_t pack2(bf16 a, bf16 b) {
    __nv_bfloat162 t; t.x = a; t.y = b;
    return *reinterpret_cast<uint32_t*>(&t);
}
__device__ __forceinline__ void mma_bf16(float d[4], const uint32_t a[4], const uint32_t b[2]) {
    asm volatile("mma.sync.aligned.m16n8k16.row.col.f32.bf16.bf16.f32 "
                 "{%0,%1,%2,%3}, {%4,%5,%6,%7}, {%8,%9}, {%0,%1,%2,%3};"
                 : "+f"(d[0]), "+f"(d[1]), "+f"(d[2]), "+f"(d[3])
                 : "r"(a[0]), "r"(a[1]), "r"(a[2]), "r"(a[3]), "r"(b[0]), "r"(b[1]));
}
__device__ __forceinline__ void ldsm4(uint32_t r[4], uint32_t addr) {
    asm volatile("ldmatrix.sync.aligned.m8n8.x4.shared.b16 {%0,%1,%2,%3}, [%4];"
                 : "=r"(r[0]), "=r"(r[1]), "=r"(r[2]), "=r"(r[3]) : "r"(addr));
}
__device__ __forceinline__ void ldsm4t(uint32_t r[4], uint32_t addr) {
    asm volatile("ldmatrix.sync.aligned.m8n8.x4.trans.shared.b16 {%0,%1,%2,%3}, [%4];"
                 : "=r"(r[0]), "=r"(r[1]), "=r"(r[2]), "=r"(r[3]) : "r"(addr));
}
__device__ __forceinline__ uint32_t s2u(const void* p) {
    return (uint32_t)__cvta_generic_to_shared(p);
}
__device__ __forceinline__ void cpa16(uint32_t dst, const void* src) {
    asm volatile("cp.async.cg.shared.global [%0], [%1], 16;" :: "r"(dst), "l"(src));
}
__device__ __forceinline__ void cp_commit() {
    asm volatile("cp.async.commit_group;");
}
template <int N>
__device__ __forceinline__ void cp_wait() {
    asm volatile("cp.async.wait_group %0;" :: "n"(N));
}

// ---------------- weight convert: fp32 -> bf16 hi/lo ----------------
__global__ void k_cvt(const float* __restrict__ x, bf16* __restrict__ hi,
                      bf16* __restrict__ lo, int n)
{
    int i = blockIdx.x * 256 + threadIdx.x;
    if (i < n) { bf16 h, l; fsplit(x[i], h, l); hi[i] = h; lo[i] = l; }
}

// ---------------- depthwise 3x3 (pad 1); 4 px/thread; emit dw & fmap hi/lo ----------------
__global__ void __launch_bounds__(256) k_dwconv(const float* __restrict__ in,
                                                const float* __restrict__ wdw)
{
    int plane = blockIdx.y;              // b*256 + c
    int c = plane & 255;
    const float* ip = in + (size_t)plane * N_PIX;

    float w[9];
#pragma unroll
    for (int k = 0; k < 9; ++k) w[k] = __ldg(wdw + c * 9 + k);

    int p4 = (blockIdx.x * 256 + threadIdx.x) * 4;
    int y = p4 >> 7, x0 = p4 & 127;

    float L[3][6];
#pragma unroll
    for (int r = 0; r < 3; ++r) {
        int yy = y + r - 1;
        if (yy < 0 || yy > 127) {
#pragma unroll
            for (int j = 0; j < 6; ++j) L[r][j] = 0.f;
        } else {
            const float* rp = ip + yy * 128 + x0;
            float4 f = *(const float4*)rp;
            L[r][1] = f.x; L[r][2] = f.y; L[r][3] = f.z; L[r][4] = f.w;
            L[r][0] = (x0 > 0)   ? __ldg(rp - 1) : 0.f;
            L[r][5] = (x0 < 124) ? __ldg(rp + 4) : 0.f;
        }
    }

    bf16 h[4], l[4];
    size_t o = (size_t)plane * N_PIX + p4;
#pragma unroll
    for (int i = 0; i < 4; ++i) {
        float s = 0.f;
#pragma unroll
        for (int r = 0; r < 3; ++r)
#pragma unroll
            for (int dx = 0; dx < 3; ++dx)
                s += L[r][i + dx] * w[r * 3 + dx];
        fsplit(s, h[i], l[i]);
    }
    *(uint2*)(g_dwhi + o) = make_uint2(pack2(h[0], h[1]), pack2(h[2], h[3]));
    *(uint2*)(g_dwlo + o) = make_uint2(pack2(l[0], l[1]), pack2(l[2], l[3]));
#pragma unroll
    for (int i = 0; i < 4; ++i) fsplit(L[1][1 + i], h[i], l[i]);
    *(uint2*)(g_fhi + o) = make_uint2(pack2(h[0], h[1]), pack2(h[2], h[3]));
    *(uint2*)(g_flo + o) = make_uint2(pack2(l[0], l[1]), pack2(l[2], l[3]));
}

// ---------------- split-bf16 tensor-core GEMM with 2-stage cp.async pipeline ----------------
// Y[o,p] = sum_c A[o,c] * X[c,p].  A hi/lo row-major [O,C]; X hi/lo [C,N_PIX].
// MODE: 0 fp32 out, 1 hl out, 2 gelu+hl out, 3 bias+fp32 out, 4 softmax-over-d(64)+scale+hl out.
template <int BM, int MODE>
__global__ void __launch_bounds__(256, 2) k_mma_gemm(
    const bf16* __restrict__ Ahi, const bf16* __restrict__ Alo,
    const bf16* __restrict__ Bhi, const bf16* __restrict__ Blo,
    const float* __restrict__ bias,
    float* __restrict__ Yf, bf16* __restrict__ Yhi, bf16* __restrict__ Ylo,
    int C, long long as_, long long xs, long long ys)
{
    constexpr int BN = 128, BK = 32, AP = 40, BP = 136;
    constexpr int WM = BM / 2, MT = WM / 16;
    constexpr uint32_t APl = BM * AP * 2;   // bytes per A plane
    constexpr uint32_t BPl = BK * BP * 2;

    extern __shared__ __align__(16) bf16 smp[];

    const int t = threadIdx.x, warp = t >> 5, lane = t & 31;
    const int wm = warp & 1, wn = warp >> 1;
    const int g = lane >> 2, tig = lane & 3;
    const int pblk = blockIdx.x * BN, o0 = blockIdx.y * BM;
    const long long z = blockIdx.z;
    const bf16* AH = Ahi + z * as_;
    const bf16* AL = Alo + z * as_;
    const bf16* XH = Bhi + z * xs;
    const bf16* XL = Blo + z * xs;

    const uint32_t Abase = s2u(smp);
    const uint32_t Bbase = Abase + 4 * APl;

#define LOAD_STAGE(st, c0v) do {                                              \
    uint32_t aD = Abase + (uint32_t)(st) * 2 * APl;                           \
    uint32_t bD = Bbase + (uint32_t)(st) * 2 * BPl;                           \
    for (int i = t; i < BM * 4; i += 256) {                                   \
        int m_ = i >> 2, kq = (i & 3) * 8;                                    \
        size_t src = (size_t)(o0 + m_) * C + (c0v) + kq;                      \
        uint32_t d_ = (uint32_t)(m_ * AP + kq) * 2;                           \
        cpa16(aD + d_, AH + src);                                             \
        cpa16(aD + APl + d_, AL + src);                                       \
    }                                                                         \
    for (int i = t; i < 512; i += 256) {                                      \
        int cc = i >> 4, pq = (i & 15) * 8;                                   \
        size_t src = (size_t)((c0v) + cc) * N_PIX + pblk + pq;                \
        uint32_t d_ = (uint32_t)(cc * BP + pq) * 2;                           \
        cpa16(bD + d_, XH + src);                                             \
        cpa16(bD + BPl + d_, XL + src);                                       \
    }                                                                         \
    cp_commit();                                                              \
} while (0)

    float acc[MT][4][4];
#pragma unroll
    for (int m = 0; m < MT; ++m)
#pragma unroll
        for (int n = 0; n < 4; ++n)
#pragma unroll
            for (int r = 0; r < 4; ++r) acc[m][n][r] = 0.f;

    const int l15 = lane & 15;
    const int hi8 = (lane >> 4) * 8;

    const int T = C >> 5;
    LOAD_STAGE(0, 0);

    for (int it = 0; it < T; ++it) {
        const int st = it & 1;
        if (it + 1 < T) { LOAD_STAGE(st ^ 1, (it + 1) * BK); cp_wait<1>(); }
        else cp_wait<0>();
        __syncthreads();

        const uint32_t a0 = Abase + (uint32_t)st * 2 * APl;
        const uint32_t a1 = a0 + APl;
        const uint32_t b0 = Bbase + (uint32_t)st * 2 * BPl;
        const uint32_t b1 = b0 + BPl;

#pragma unroll
        for (int ks = 0; ks < BK; ks += 16) {
            uint32_t bh_[4][2], bl_[4][2], r[4];
#pragma unroll
            for (int nn = 0; nn < 2; ++nn) {
                uint32_t off = (uint32_t)((ks + l15) * BP + wn * 32 + nn * 16 + hi8) * 2;
                ldsm4t(r, b0 + off);
                bh_[nn*2][0] = r[0]; bh_[nn*2][1] = r[1];
                bh_[nn*2+1][0] = r[2]; bh_[nn*2+1][1] = r[3];
                ldsm4t(r, b1 + off);
                bl_[nn*2][0] = r[0]; bl_[nn*2][1] = r[1];
                bl_[nn*2+1][0] = r[2]; bl_[nn*2+1][1] = r[3];
            }
#pragma unroll
            for (int mt = 0; mt < MT; ++mt) {
                uint32_t ah[4], al[4];
                uint32_t off = (uint32_t)((wm * WM + mt * 16 + l15) * AP + ks + hi8) * 2;
                ldsm4(ah, a0 + off);
                ldsm4(al, a1 + off);
#pragma unroll
                for (int nt = 0; nt < 4; ++nt) {
                    mma_bf16(acc[mt][nt], ah, bh_[nt]);
                    mma_bf16(acc[mt][nt], al, bh_[nt]);
                    mma_bf16(acc[mt][nt], ah, bl_[nt]);
                }
            }
        }
        __syncthreads();
    }
#undef LOAD_STAGE

    if (MODE == 4) {
        // softmax over the 64 rows of this warp-half (one head), per pixel column; *1/8
        float sc[8];
#pragma unroll
        for (int nt = 0; nt < 4; ++nt)
#pragma unroll
            for (int c = 0; c < 2; ++c) {
                float m = -3.4e38f;
#pragma unroll
                for (int mt = 0; mt < MT; ++mt) {
                    m = fmaxf(m, acc[mt][nt][c]);
                    m = fmaxf(m, acc[mt][nt][2 + c]);
                }
                m = fmaxf(m, __shfl_xor_sync(0xffffffffu, m, 4));
                m = fmaxf(m, __shfl_xor_sync(0xffffffffu, m, 8));
                m = fmaxf(m, __shfl_xor_sync(0xffffffffu, m, 16));
                float s = 0.f;
#pragma unroll
                for (int mt = 0; mt < MT; ++mt) {
                    float e0 = expf(acc[mt][nt][c] - m);
                    float e1 = expf(acc[mt][nt][2 + c] - m);
                    acc[mt][nt][c] = e0; acc[mt][nt][2 + c] = e1;
                    s += e0 + e1;
                }
                s += __shfl_xor_sync(0xffffffffu, s, 4);
                s += __shfl_xor_sync(0xffffffffu, s, 8);
                s += __shfl_xor_sync(0xffffffffu, s, 16);
                sc[nt * 2 + c] = 0.125f / s;
            }
#pragma unroll
        for (int mt = 0; mt < MT; ++mt)
#pragma unroll
            for (int h2 = 0; h2 < 2; ++h2) {
                int rrow = o0 + wm * WM + mt * 16 + g + h2 * 8;
#pragma unroll
                for (int nt = 0; nt < 4; ++nt) {
                    int p = pblk + wn * 32 + nt * 8 + tig * 2;
                    float v0 = acc[mt][nt][h2 * 2 + 0] * sc[nt * 2 + 0];
                    float v1 = acc[mt][nt][h2 * 2 + 1] * sc[nt * 2 + 1];
                    size_t o = (size_t)rrow * N_PIX + p;
                    bf16 h0, l0, h1, l1;
                    fsplit(v0, h0, l0); fsplit(v1, h1, l1);
                    *(uint32_t*)(Yhi + z * ys + o) = pack2(h0, h1);
                    *(uint32_t*)(Ylo + z * ys + o) = pack2(l0, l1);
                }
            }
        return;
    }

#pragma unroll
    for (int mt = 0; mt < MT; ++mt) {
#pragma unroll
        for (int h2 = 0; h2 < 2; ++h2) {
            int rrow = o0 + wm * WM + mt * 16 + g + h2 * 8;
            float bb = (MODE == 3) ? __ldg(&bias[rrow]) : 0.f;
#pragma unroll
            for (int nt = 0; nt < 4; ++nt) {
                int p = pblk + wn * 32 + nt * 8 + tig * 2;
                float v0 = acc[mt][nt][h2 * 2 + 0] + bb;
                float v1 = acc[mt][nt][h2 * 2 + 1] + bb;
                size_t o = (size_t)rrow * N_PIX + p;
                if (MODE == 0 || MODE == 3) {
                    *(float2*)(Yf + z * ys + o) = make_float2(v0, v1);
                } else {
                    if (MODE == 2) { v0 = gelu_exact(v0); v1 = gelu_exact(v1); }
                    bf16 h0, l0, h1, l1;
                    fsplit(v0, h0, l0); fsplit(v1, h1, l1);
                    *(uint32_t*)(Yhi + z * ys + o) = pack2(h0, h1);
                    *(uint32_t*)(Ylo + z * ys + o) = pack2(l0, l1);
                }
            }
        }
    }
}

// ---------------- softmax over spatial N (16384) for k; emit hi/lo ----------------
__global__ void __launch_bounds__(256) k_softmax_k(const float* __restrict__ kin,
                                                   bf16* __restrict__ khi, bf16* __restrict__ klo)
{
    int row = blockIdx.x;
    const float4* b4 = (const float4*)(kin + (size_t)row * N_PIX);
    size_t ob = (size_t)row * N_PIX;
    int t = threadIdx.x, lane = t & 31, warp = t >> 5;
    __shared__ float red[40];

    float4 r[16];
    float m = -3.4e38f;
#pragma unroll
    for (int i = 0; i < 16; ++i) {
        r[i] = b4[t + i * 256];
        m = fmaxf(m, fmaxf(fmaxf(r[i].x, r[i].y), fmaxf(r[i].z, r[i].w)));
    }
#pragma unroll
    for (int o = 16; o; o >>= 1) m = fmaxf(m, __shfl_xor_sync(0xffffffffu, m, o));
    if (lane == 0) red[warp] = m;
    __syncthreads();
    if (t == 0) { float mm = red[0]; for (int w = 1; w < 8; ++w) mm = fmaxf(mm, red[w]); red[32] = mm; }
    __syncthreads();
    m = red[32];

    float s = 0.f;
#pragma unroll
    for (int i = 0; i < 16; ++i) {
        r[i].x = expf(r[i].x - m); r[i].y = expf(r[i].y - m);
        r[i].z = expf(r[i].z - m); r[i].w = expf(r[i].w - m);
        s += r[i].x + r[i].y + r[i].z + r[i].w;
    }
#pragma unroll
    for (int o = 16; o; o >>= 1) s += __shfl_xor_sync(0xffffffffu, s, o);
    if (lane == 0) red[warp] = s;
    __syncthreads();
    if (t == 0) { float tt = 0.f; for (int w = 0; w < 8; ++w) tt += red[w]; red[33] = tt; }
    __syncthreads();
    float inv = 1.0f / red[33];
#pragma unroll
    for (int i = 0; i < 16; ++i) {
        bf16 h0, l0, h1, l1, h2, l2, h3, l3;
        fsplit(r[i].x * inv, h0, l0); fsplit(r[i].y * inv, h1, l1);
        fsplit(r[i].z * inv, h2, l2); fsplit(r[i].w * inv, h3, l3);
        size_t o = ob + (size_t)(t + i * 256) * 4;
        *(uint2*)(khi + o) = make_uint2(pack2(h0, h1), pack2(h2, h3));
        *(uint2*)(klo + o) = make_uint2(pack2(l0, l1), pack2(l2, l3));
    }
}

// ---------------- context partials (tensor, pipelined): P[bh,s][e][d] ----------------
__global__ void __launch_bounds__(256, 2) k_ctx_t(
    const bf16* __restrict__ khi, const bf16* __restrict__ klo,
    const bf16* __restrict__ vhi, const bf16* __restrict__ vlo,
    float* __restrict__ part)
{
    constexpr int P = 72;
    constexpr uint32_t ASZ = 64 * P * 2;          // bytes per array
    extern __shared__ __align__(16) bf16 smp[];

    int t = threadIdx.x, warp = t >> 5, lane = t & 31;
    int wm = warp & 1, wn = warp >> 1;
    int g = lane >> 2, tig = lane & 3;
    int bh = blockIdx.x >> 3, s = blockIdx.x & 7;
    size_t cb = (size_t)bh * 64 * N_PIX + (size_t)s * 2048;

    const uint32_t base = s2u(smp);
#define CARR(st, a) (base + ((uint32_t)(st) * 4 + (a)) * ASZ)

#define CTX_LOAD(st, itv) do {                                                \
    for (int i = t; i < 512; i += 256) {                                      \
        int row = i >> 3, c8 = (i & 7) * 8;                                   \
        size_t src = cb + (size_t)row * N_PIX + (itv) * 64 + c8;              \
        uint32_t d_ = (uint32_t)(row * P + c8) * 2;                           \
        cpa16(CARR(st, 0) + d_, khi + src);                                   \
        cpa16(CARR(st, 1) + d_, klo + src);                                   \
        cpa16(CARR(st, 2) + d_, vhi + src);                                   \
        cpa16(CARR(st, 3) + d_, vlo + src);                                   \
    }                                                                         \
    cp_commit();                                                              \
} while (0)

    float acc[2][2][4];
#pragma unroll
    for (int m = 0; m < 2; ++m)
#pragma unroll
        for (int n = 0; n < 2; ++n)
#pragma unroll
            for (int r = 0; r < 4; ++r) acc[m][n][r] = 0.f;

    const int l15 = lane & 15, hi8 = (lane >> 4) * 8;
    const int bg = lane >> 3, bl = lane & 7;
    const int brow = (bg >> 1) * 8 + bl;
    const int bcol = (bg & 1) * 8;

    CTX_LOAD(0, 0);
    for (int it = 0; it < 32; ++it) {
        int st = it & 1;
        if (it + 1 < 32) { CTX_LOAD(st ^ 1, it + 1); cp_wait<1>(); }
        else cp_wait<0>();
        __syncthreads();

        const uint32_t kB0 = CARR(st, 0), kB1 = CARR(st, 1);
        const uint32_t vB0 = CARR(st, 2), vB1 = CARR(st, 3);

#pragma unroll
        for (int ks = 0; ks < 64; ks += 16) {
            uint32_t bh_[2][2], bl_[2][2], r[4];
            uint32_t boff = (uint32_t)((wn * 16 + brow) * P + ks + bcol) * 2;
            ldsm4(r, kB0 + boff);
            bh_[0][0] = r[0]; bh_[0][1] = r[1]; bh_[1][0] = r[2]; bh_[1][1] = r[3];
            ldsm4(r, kB1 + boff);
            bl_[0][0] = r[0]; bl_[0][1] = r[1]; bl_[1][0] = r[2]; bl_[1][1] = r[3];
#pragma unroll
            for (int mt = 0; mt < 2; ++mt) {
                uint32_t ah[4], al[4];
                uint32_t aoff = (uint32_t)((wm * 32 + mt * 16 + l15) * P + ks + hi8) * 2;
                ldsm4(ah, vB0 + aoff);
                ldsm4(al, vB1 + aoff);
#pragma unroll
                for (int nt = 0; nt < 2; ++nt) {
                    mma_bf16(acc[mt][nt], ah, bh_[nt]);
                    mma_bf16(acc[mt][nt], al, bh_[nt]);
                    mma_bf16(acc[mt][nt], ah, bl_[nt]);
                }
            }
        }
        __syncthreads();
    }
#undef CTX_LOAD
#undef CARR

    size_t ob = (size_t)blockIdx.x * 4096;
#pragma unroll
    for (int mt = 0; mt < 2; ++mt)
#pragma unroll
        for (int h2 = 0; h2 < 2; ++h2) {
            int e = wm * 32 + mt * 16 + g + h2 * 8;
#pragma unroll
            for (int nt = 0; nt < 2; ++nt) {
                int d = wn * 16 + nt * 8 + tig * 2;
                *(float2*)&part[ob + (size_t)e * 64 + d] =
                    make_float2(acc[mt][nt][h2 * 2], acc[mt][nt][h2 * 2 + 1]);
            }
        }
}

// ---------------- reduce partials; emit ctx^T hi/lo [bh][e][d] ----------------
__global__ void k_ctx_reduce(const float* __restrict__ part,
                             bf16* __restrict__ chi, bf16* __restrict__ clo)
{
    int i = blockIdx.x * 256 + threadIdx.x;
    int bh = i >> 12, ed = i & 4095;
    float s = 0.f;
#pragma unroll
    for (int ss = 0; ss < 8; ++ss)
        s += part[((size_t)bh * 8 + ss) * 4096 + ed];
    bf16 h, l; fsplit(s, h, l);
    chi[i] = h; clo[i] = l;
}

// ---------------- launch ----------------
extern "C" void kernel_launch(void* const* d_in, const int* in_sizes, int n_in,
                              void* d_out, int out_size)
{
    const float* fmap  = (const float*)d_in[0];
    const float* w_q   = (const float*)d_in[1];
    const float* w_dw  = (const float*)d_in[2];
    const float* w_pw  = (const float*)d_in[3];
    const float* w_out = (const float*)d_in[4];
    const float* b_out = (const float*)d_in[5];
    float* out = (float*)d_out;

    float *k, *part;
    bf16 *fhi, *flo, *dwhi, *dwlo, *qhi, *qlo, *khi, *klo, *vhi, *vlo;
    bf16 *avhi, *avlo, *chi, *clo, *wqh, *wql, *wph, *wpl, *woh, *wol;
    cudaGetSymbolAddress((void**)&k,    g_k);
    cudaGetSymbolAddress((void**)&part, g_part);
    cudaGetSymbolAddress((void**)&fhi,  g_fhi);   cudaGetSymbolAddress((void**)&flo,  g_flo);
    cudaGetSymbolAddress((void**)&dwhi, g_dwhi);  cudaGetSymbolAddress((void**)&dwlo, g_dwlo);
    cudaGetSymbolAddress((void**)&qhi,  g_qhi);   cudaGetSymbolAddress((void**)&qlo,  g_qlo);
    cudaGetSymbolAddress((void**)&khi,  g_khi);   cudaGetSymbolAddress((void**)&klo,  g_klo);
    cudaGetSymbolAddress((void**)&vhi,  g_vhi);   cudaGetSymbolAddress((void**)&vlo,  g_vlo);
    cudaGetSymbolAddress((void**)&avhi, g_avhi);  cudaGetSymbolAddress((void**)&avlo, g_avlo);
    cudaGetSymbolAddress((void**)&chi,  g_ctxhi); cudaGetSymbolAddress((void**)&clo,  g_ctxlo);
    cudaGetSymbolAddress((void**)&wqh,  g_wqhi);  cudaGetSymbolAddress((void**)&wql,  g_wqlo);
    cudaGetSymbolAddress((void**)&wph,  g_wpwhi); cudaGetSymbolAddress((void**)&wpl,  g_wpwlo);
    cudaGetSymbolAddress((void**)&woh,  g_wohi);  cudaGetSymbolAddress((void**)&wol,  g_wolo);

    const int SM128 = 8 * (40 * 128 + 4352);   // 75776 B
    const int SM64  = 8 * (40 * 64 + 4352);    // 55296 B
    const int SMCTX = 2 * 4 * 64 * 72 * 2;     // 73728 B
    cudaFuncSetAttribute(k_mma_gemm<128,4>, cudaFuncAttributeMaxDynamicSharedMemorySize, SM128);
    cudaFuncSetAttribute(k_mma_gemm<128,0>, cudaFuncAttributeMaxDynamicSharedMemorySize, SM128);
    cudaFuncSetAttribute(k_mma_gemm<128,1>, cudaFuncAttributeMaxDynamicSharedMemorySize, SM128);
    cudaFuncSetAttribute(k_mma_gemm<128,3>, cudaFuncAttributeMaxDynamicSharedMemorySize, SM128);
    cudaFuncSetAttribute(k_mma_gemm<64,2>,  cudaFuncAttributeMaxDynamicSharedMemorySize, SM64);
    cudaFuncSetAttribute(k_ctx_t,           cudaFuncAttributeMaxDynamicSharedMemorySize, SMCTX);

    // 0) weight splits
    k_cvt<<<512, 256>>>(w_q, wqh, wql, 512 * 256);
    k_cvt<<<1024, 256>>>(w_pw, wph, wpl, 1024 * 256);
    k_cvt<<<512, 256>>>(w_out, woh, wol, 256 * 512);

    // 1) depthwise 3x3 + fmap/dw hi-lo planes (4 px/thread)
    k_dwconv<<<dim3(16, BATCH * 256), 256>>>(fmap, w_dw);

    // 2) q = softmax_d(w_q @ fmap) * 1/8  (fused, hl out)
    k_mma_gemm<128, 4><<<dim3(128, 4, 8), 256, SM128>>>(
        wqh, wql, fhi, flo, nullptr, nullptr, qhi, qlo,
        256, 0, 256LL * N_PIX, 512LL * N_PIX);

    // 3a) k = w_pw[0:512] @ dw  (fp32 out)
    k_mma_gemm<128, 0><<<dim3(128, 4, 8), 256, SM128>>>(
        wph, wpl, dwhi, dwlo, nullptr, k, nullptr, nullptr,
        256, 0, 256LL * N_PIX, 512LL * N_PIX);

    // 3b) v = w_pw[512:1024] @ dw  (hl out)
    k_mma_gemm<128, 1><<<dim3(128, 4, 8), 256, SM128>>>(
        wph + 512 * 256, wpl + 512 * 256, dwhi, dwlo, nullptr,
        nullptr, vhi, vlo, 256, 0, 256LL * N_PIX, 512LL * N_PIX);

    // 4) softmax over N for k -> hi/lo
    k_softmax_k<<<4096, 256>>>(k, khi, klo);

    // 5) context: pipelined tensor split-K partials + reduce
    k_ctx_t<<<512, 256, SMCTX>>>(khi, klo, vhi, vlo, part);
    k_ctx_reduce<<<1024, 256>>>(part, chi, clo);

    // 6) av = gelu(ctx^T @ q)  batched over 64 (b,h)  (hl out)
    k_mma_gemm<64, 2><<<dim3(128, 1, 64), 256, SM64>>>(
        chi, clo, qhi, qlo, nullptr, nullptr, avhi, avlo,
        64, 4096LL, 64LL * N_PIX, 64LL * N_PIX);

    // 7) out = w_out @ av + b_out  (fp32 + bias)
    k_mma_gemm<128, 3><<<dim3(128, 2, 8), 256, SM128>>>(
        woh, wol, avhi, avlo, b_out, out, nullptr, nullptr,
        512, 0, 512LL * N_PIX, 256LL * N_PIX);
}